// round 4
// baseline (speedup 1.0000x reference)
#include <cuda_runtime.h>
#include <cuda_bf16.h>
#include <cstdint>
#include <math.h>

#define MTOK 8192
#define DMODEL 1024
#define NH 16
#define DK 64
#define HID 4096
#define SEQ 2048
#define KP1 (3 * DMODEL)   /* 3072  */
#define KP2 (3 * HID)      /* 12288 */

// ---------------------------------------------------------------------------
// Scratch (__device__ globals; allocation is forbidden)
// ---------------------------------------------------------------------------
__device__ __nv_bfloat16 g_xn_s[MTOK * KP1];          // rmsnorm out, split
__device__ float         g_q[MTOK * DMODEL];
__device__ float         g_k[MTOK * DMODEL];
__device__ float         g_v[MTOK * DMODEL];
__device__ __nv_bfloat16 g_attn_s[MTOK * KP1];        // attention out, split
__device__ float         g_h[MTOK * DMODEL];          // residual 1
__device__ __nv_bfloat16 g_y_s[MTOK * KP1];           // layernorm out, split
__device__ __nv_bfloat16 g_hid_s[(long)MTOK * KP2];   // relu(ffn1) out, split
__device__ __nv_bfloat16 g_wq[DMODEL * KP1];
__device__ __nv_bfloat16 g_wk[DMODEL * KP1];
__device__ __nv_bfloat16 g_wv[DMODEL * KP1];
__device__ __nv_bfloat16 g_wpost[DMODEL * KP1];
__device__ __nv_bfloat16 g_w1[HID * KP1];
__device__ __nv_bfloat16 g_w2[DMODEL * KP2];

// ---------------------------------------------------------------------------
// Helpers
// ---------------------------------------------------------------------------
__device__ __forceinline__ uint32_t s2u(const void* p) {
    uint32_t a;
    asm("{ .reg .u64 t; cvta.to.shared.u64 t, %1; cvt.u32.u64 %0, t; }"
        : "=r"(a) : "l"(p));
    return a;
}
#define SW128(o) ((o) ^ (((o) >> 3) & 0x70))

__device__ __forceinline__ void split2(float f, __nv_bfloat16& h, __nv_bfloat16& l) {
    h = __float2bfloat16(f);
    l = __float2bfloat16(f - __bfloat162float(h));
}
__device__ __forceinline__ __nv_bfloat162 mk2(__nv_bfloat16 a, __nv_bfloat16 b) {
    __nv_bfloat162 r; r.x = a; r.y = b; return r;
}

// ---------------------------------------------------------------------------
// Weight split: W fp32 [R,K] -> bf16 [R,3K] as [hi, hi, lo]
// ---------------------------------------------------------------------------
__global__ __launch_bounds__(256) void split_w_kernel(
    const float* __restrict__ W, __nv_bfloat16* __restrict__ out,
    int K, long total4) {
    long idx = blockIdx.x * 256L + threadIdx.x;
    if (idx >= total4) return;
    int kq = K >> 2;
    long m = idx / kq;
    int kk = (int)(idx % kq) << 2;
    float4 v = *(const float4*)(W + m * K + kk);
    __nv_bfloat16 h0, l0, h1, l1, h2, l2, h3, l3;
    split2(v.x, h0, l0); split2(v.y, h1, l1);
    split2(v.z, h2, l2); split2(v.w, h3, l3);
    __nv_bfloat16* o = out + m * (long)(3 * K) + kk;
    *(__nv_bfloat162*)(o) = mk2(h0, h1);
    *(__nv_bfloat162*)(o + 2) = mk2(h2, h3);
    *(__nv_bfloat162*)(o + K) = mk2(h0, h1);
    *(__nv_bfloat162*)(o + K + 2) = mk2(h2, h3);
    *(__nv_bfloat162*)(o + 2 * K) = mk2(l0, l1);
    *(__nv_bfloat162*)(o + 2 * K + 2) = mk2(l2, l3);
}

// ---------------------------------------------------------------------------
// RMSNorm -> split bf16 [M, 3K] as [hi, lo, hi]
// ---------------------------------------------------------------------------
__global__ __launch_bounds__(256) void rmsnorm_split_kernel(
    const float* __restrict__ x, const float* __restrict__ scale,
    __nv_bfloat16* __restrict__ out) {
    int row = blockIdx.x;
    int tid = threadIdx.x;
    float4 v = ((const float4*)(x + (long)row * DMODEL))[tid];
    float ss = v.x * v.x + v.y * v.y + v.z * v.z + v.w * v.w;
#pragma unroll
    for (int w = 16; w; w >>= 1) ss += __shfl_xor_sync(0xffffffffu, ss, w);
    __shared__ float red[8];
    if ((tid & 31) == 0) red[tid >> 5] = ss;
    __syncthreads();
    float tot = 0.f;
#pragma unroll
    for (int i = 0; i < 8; i++) tot += red[i];
    float r = rsqrtf(tot * (1.0f / 1024.0f) + 1e-6f);
    float4 sc = ((const float4*)scale)[tid];
    float f0 = v.x * r * sc.x, f1 = v.y * r * sc.y;
    float f2 = v.z * r * sc.z, f3 = v.w * r * sc.w;
    __nv_bfloat16 h0, l0, h1, l1, h2, l2, h3, l3;
    split2(f0, h0, l0); split2(f1, h1, l1);
    split2(f2, h2, l2); split2(f3, h3, l3);
    __nv_bfloat16* o = out + (long)row * KP1 + tid * 4;
    *(__nv_bfloat162*)(o) = mk2(h0, h1);
    *(__nv_bfloat162*)(o + 2) = mk2(h2, h3);
    *(__nv_bfloat162*)(o + DMODEL) = mk2(l0, l1);
    *(__nv_bfloat162*)(o + DMODEL + 2) = mk2(l2, l3);
    *(__nv_bfloat162*)(o + 2 * DMODEL) = mk2(h0, h1);
    *(__nv_bfloat162*)(o + 2 * DMODEL + 2) = mk2(h2, h3);
}

// ---------------------------------------------------------------------------
// LayerNorm -> split bf16 [M, 3K]
// ---------------------------------------------------------------------------
__global__ __launch_bounds__(256) void layernorm_split_kernel(
    const float* __restrict__ x, const float* __restrict__ scale,
    const float* __restrict__ bias, __nv_bfloat16* __restrict__ out) {
    int row = blockIdx.x;
    int tid = threadIdx.x;
    float4 v = ((const float4*)(x + (long)row * DMODEL))[tid];
    float s = v.x + v.y + v.z + v.w;
    float sq = v.x * v.x + v.y * v.y + v.z * v.z + v.w * v.w;
#pragma unroll
    for (int w = 16; w; w >>= 1) {
        s += __shfl_xor_sync(0xffffffffu, s, w);
        sq += __shfl_xor_sync(0xffffffffu, sq, w);
    }
    __shared__ float rs[8], rq[8];
    if ((tid & 31) == 0) { rs[tid >> 5] = s; rq[tid >> 5] = sq; }
    __syncthreads();
    float S = 0.f, Q = 0.f;
#pragma unroll
    for (int i = 0; i < 8; i++) { S += rs[i]; Q += rq[i]; }
    float mean = S * (1.0f / 1024.0f);
    float var = Q * (1.0f / 1024.0f) - mean * mean;
    float r = rsqrtf(var + 1e-6f);
    float4 sc = ((const float4*)scale)[tid];
    float4 bi = ((const float4*)bias)[tid];
    float f0 = (v.x - mean) * r * (1.0f + sc.x) + bi.x;
    float f1 = (v.y - mean) * r * (1.0f + sc.y) + bi.y;
    float f2 = (v.z - mean) * r * (1.0f + sc.z) + bi.z;
    float f3 = (v.w - mean) * r * (1.0f + sc.w) + bi.w;
    __nv_bfloat16 h0, l0, h1, l1, h2, l2, h3, l3;
    split2(f0, h0, l0); split2(f1, h1, l1);
    split2(f2, h2, l2); split2(f3, h3, l3);
    __nv_bfloat16* o = out + (long)row * KP1 + tid * 4;
    *(__nv_bfloat162*)(o) = mk2(h0, h1);
    *(__nv_bfloat162*)(o + 2) = mk2(h2, h3);
    *(__nv_bfloat162*)(o + DMODEL) = mk2(l0, l1);
    *(__nv_bfloat162*)(o + DMODEL + 2) = mk2(l2, l3);
    *(__nv_bfloat162*)(o + 2 * DMODEL) = mk2(h0, h1);
    *(__nv_bfloat162*)(o + 2 * DMODEL + 2) = mk2(h2, h3);
}

// ---------------------------------------------------------------------------
// mma.sync bf16 GEMM: C[m,n] = sum_k A[m,k]*B[n,k] (+bias)(+relu)(+res)
// A [M,Kp], B [N,Kp] bf16 row-major. 128x128 CTA tile, BK=64, cp.async
// double-buffered, 8 warps (2m x 4n), warp tile 64x32 via m16n8k16.
// SPLIT: write bf16 [hi,lo,hi] at pitch 3N instead of fp32.
// ---------------------------------------------------------------------------
template <bool RELU, bool RES, bool SPLIT>
__global__ void __launch_bounds__(256, 2) gemm_mma(
    const __nv_bfloat16* __restrict__ A, const __nv_bfloat16* __restrict__ Bw,
    const float* __restrict__ bias, const float* __restrict__ res,
    float* __restrict__ Cf, __nv_bfloat16* __restrict__ Cs, int N, int Kp) {
    extern __shared__ char smem[];
    uint32_t sbase = s2u(smem);
    int tid = threadIdx.x;
    int wid = tid >> 5, lane = tid & 31;
    int wm = (wid & 1) * 64;
    int wn = (wid >> 1) * 32;
    long row0 = (long)blockIdx.y * 128, col0 = (long)blockIdx.x * 128;
    const __nv_bfloat16* Ab = A + row0 * (long)Kp;
    const __nv_bfloat16* Bb = Bw + col0 * (long)Kp;

    // cp.async mapping: 2 threads per 128B row, 4x16B chunks each
    int ldr = tid >> 1;
    int ldc = (tid & 1) * 4;

    auto issue = [&](int c, int s) {
        long kc = (long)c << 6;
        uint32_t abase = sbase + (uint32_t)s * 32768u;
        uint32_t bbase = abase + 16384u;
        const __nv_bfloat16* ag = Ab + (long)ldr * Kp + kc + ldc * 8;
        const __nv_bfloat16* bg = Bb + (long)ldr * Kp + kc + ldc * 8;
#pragma unroll
        for (int i = 0; i < 4; i++) {
            uint32_t off = SW128((uint32_t)(ldr * 128 + (ldc + i) * 16));
            asm volatile("cp.async.cg.shared.global [%0], [%1], 16;"
                         :: "r"(abase + off), "l"(ag + i * 8) : "memory");
            asm volatile("cp.async.cg.shared.global [%0], [%1], 16;"
                         :: "r"(bbase + off), "l"(bg + i * 8) : "memory");
        }
        asm volatile("cp.async.commit_group;" ::: "memory");
    };

    float acc[4][4][4] = {};
    const int C = Kp >> 6;

    issue(0, 0);
    for (int c = 0; c < C; c++) {
        if (c + 1 < C) {
            issue(c + 1, (c + 1) & 1);
            asm volatile("cp.async.wait_group 1;" ::: "memory");
        } else {
            asm volatile("cp.async.wait_group 0;" ::: "memory");
        }
        __syncthreads();
        uint32_t abase = sbase + (uint32_t)(c & 1) * 32768u;
        uint32_t bbase = abase + 16384u;
#pragma unroll
        for (int ks = 0; ks < 4; ks++) {
            uint32_t a[4][4], b[2][4];
#pragma unroll
            for (int mt = 0; mt < 4; mt++) {
                int r = wm + mt * 16 + (lane & 15);
                uint32_t off = SW128((uint32_t)(r * 128 + ks * 32 + ((lane >> 4) << 4)));
                asm volatile(
                    "ldmatrix.sync.aligned.m8n8.x4.shared.b16 {%0,%1,%2,%3}, [%4];"
                    : "=r"(a[mt][0]), "=r"(a[mt][1]), "=r"(a[mt][2]), "=r"(a[mt][3])
                    : "r"(abase + off));
            }
#pragma unroll
            for (int nt2 = 0; nt2 < 2; nt2++) {
                int nr = wn + nt2 * 16 + (lane & 7) + ((lane >> 4) << 3);
                uint32_t off = SW128(
                    (uint32_t)(nr * 128 + ks * 32 + (((lane >> 3) & 1) << 4)));
                asm volatile(
                    "ldmatrix.sync.aligned.m8n8.x4.shared.b16 {%0,%1,%2,%3}, [%4];"
                    : "=r"(b[nt2][0]), "=r"(b[nt2][1]), "=r"(b[nt2][2]), "=r"(b[nt2][3])
                    : "r"(bbase + off));
            }
#pragma unroll
            for (int mt = 0; mt < 4; mt++)
#pragma unroll
                for (int nt = 0; nt < 4; nt++) {
                    uint32_t b0 = b[nt >> 1][(nt & 1) * 2];
                    uint32_t b1 = b[nt >> 1][(nt & 1) * 2 + 1];
                    asm volatile(
                        "mma.sync.aligned.m16n8k16.row.col.f32.bf16.bf16.f32 "
                        "{%0,%1,%2,%3}, {%4,%5,%6,%7}, {%8,%9}, {%0,%1,%2,%3};"
                        : "+f"(acc[mt][nt][0]), "+f"(acc[mt][nt][1]),
                          "+f"(acc[mt][nt][2]), "+f"(acc[mt][nt][3])
                        : "r"(a[mt][0]), "r"(a[mt][1]), "r"(a[mt][2]),
                          "r"(a[mt][3]), "r"(b0), "r"(b1));
                }
        }
        __syncthreads();
    }

    // Epilogue: lane t owns rows (t/4, t/4+8), cols (t%4)*2,+1 per 16x8 tile
    int tq = lane >> 2, tr = lane & 3;
#pragma unroll
    for (int mt = 0; mt < 4; mt++) {
#pragma unroll
        for (int half = 0; half < 2; half++) {
            long row = row0 + wm + mt * 16 + tq + half * 8;
#pragma unroll
            for (int nt = 0; nt < 4; nt++) {
                int col = (int)col0 + wn + nt * 8 + tr * 2;
                float v0 = acc[mt][nt][half * 2 + 0] + bias[col];
                float v1 = acc[mt][nt][half * 2 + 1] + bias[col + 1];
                if (RELU) { v0 = fmaxf(v0, 0.f); v1 = fmaxf(v1, 0.f); }
                if (SPLIT) {
                    __nv_bfloat16 h0, l0, h1, l1;
                    split2(v0, h0, l0); split2(v1, h1, l1);
                    __nv_bfloat16* o = Cs + row * (long)(3 * N) + col;
                    *(__nv_bfloat162*)(o) = mk2(h0, h1);
                    *(__nv_bfloat162*)(o + N) = mk2(l0, l1);
                    *(__nv_bfloat162*)(o + 2 * N) = mk2(h0, h1);
                } else {
                    long idx = row * (long)N + col;
                    if (RES) {
                        float2 r2 = *(const float2*)(res + idx);
                        v0 += r2.x; v1 += r2.y;
                    }
                    float2 o2; o2.x = v0; o2.y = v1;
                    *(float2*)(Cf + idx) = o2;
                }
            }
        }
    }
}

// ---------------------------------------------------------------------------
// Flash attention (fp32), epilogue writes split bf16 [B,S,3*DMODEL]
// ---------------------------------------------------------------------------
__global__ __launch_bounds__(256) void attention_kernel(
    const float* __restrict__ q, const float* __restrict__ k,
    const float* __restrict__ v, const float* __restrict__ mask,
    const float* __restrict__ pds, __nv_bfloat16* __restrict__ out) {
    __shared__ float Qs[64][68];
    __shared__ float Ks[64][64];
    __shared__ float Vs[64][64];
    __shared__ float Ps[64][68];
    __shared__ float sscale[64];

    int tid = threadIdx.x;
    int bh = blockIdx.y;
    int b = bh >> 4, h = bh & 15;
    int q0 = blockIdx.x * 64;
    long base = (long)b * SEQ * DMODEL + h * DK;
    const float* qb = q + base;
    const float* kb = k + base;
    const float* vb = v + base;

    if (tid < 64) sscale[tid] = 0.18033688f * log1pf(__expf(pds[tid]));
    __syncthreads();

    {
        int lr = tid >> 2, ld = (tid & 3) << 4;
        const float* src = qb + (long)(q0 + lr) * DMODEL + ld;
#pragma unroll
        for (int t = 0; t < 16; t += 4) {
            float4 val = *(const float4*)(src + t);
            Qs[lr][ld + t + 0] = val.x * sscale[ld + t + 0];
            Qs[lr][ld + t + 1] = val.y * sscale[ld + t + 1];
            Qs[lr][ld + t + 2] = val.z * sscale[ld + t + 2];
            Qs[lr][ld + t + 3] = val.w * sscale[ld + t + 3];
        }
    }

    int ty = tid >> 4, tx = tid & 15;
    int r0 = ty << 2, c0 = tx << 2;
    float o[4][4] = {};
    float m[4], l[4] = {};
#pragma unroll
    for (int i = 0; i < 4; i++) m[i] = -1e30f;

    for (int k0 = 0; k0 < SEQ; k0 += 64) {
        __syncthreads();
        {
            int lr = tid >> 2, ld = (tid & 3) << 4;
            const float* ksrc = kb + (long)(k0 + lr) * DMODEL + ld;
            const float* vsrc = vb + (long)(k0 + lr) * DMODEL + ld;
#pragma unroll
            for (int t = 0; t < 16; t += 4) {
                float4 kv = *(const float4*)(ksrc + t);
                Ks[ld + t + 0][lr] = kv.x;
                Ks[ld + t + 1][lr] = kv.y;
                Ks[ld + t + 2][lr] = kv.z;
                Ks[ld + t + 3][lr] = kv.w;
                *(float4*)&Vs[lr][ld + t] = *(const float4*)(vsrc + t);
            }
        }
        __syncthreads();

        float s[4][4] = {};
#pragma unroll
        for (int kk = 0; kk < 64; kk += 4) {
            float4 qv[4];
#pragma unroll
            for (int i = 0; i < 4; i++) qv[i] = *(const float4*)&Qs[r0 + i][kk];
#pragma unroll
            for (int t = 0; t < 4; t++) {
                float4 kv = *(const float4*)&Ks[kk + t][c0];
#pragma unroll
                for (int i = 0; i < 4; i++) {
                    float qi = (t == 0) ? qv[i].x : (t == 1) ? qv[i].y
                             : (t == 2) ? qv[i].z : qv[i].w;
                    s[i][0] += qi * kv.x;
                    s[i][1] += qi * kv.y;
                    s[i][2] += qi * kv.z;
                    s[i][3] += qi * kv.w;
                }
            }
        }

#pragma unroll
        for (int i = 0; i < 4; i++) {
            float4 mk = *(const float4*)&mask[(long)(q0 + r0 + i) * SEQ + k0 + c0];
            s[i][0] += mk.x; s[i][1] += mk.y; s[i][2] += mk.z; s[i][3] += mk.w;
            float tm = fmaxf(fmaxf(s[i][0], s[i][1]), fmaxf(s[i][2], s[i][3]));
#pragma unroll
            for (int w = 8; w; w >>= 1)
                tm = fmaxf(tm, __shfl_xor_sync(0xffffffffu, tm, w));
            float nm = fmaxf(m[i], tm);
            float corr = __expf(m[i] - nm);
            float ts = 0.f;
#pragma unroll
            for (int j = 0; j < 4; j++) {
                float p = __expf(s[i][j] - nm);
                s[i][j] = p;
                ts += p;
            }
#pragma unroll
            for (int w = 8; w; w >>= 1)
                ts += __shfl_xor_sync(0xffffffffu, ts, w);
            l[i] = l[i] * corr + ts;
            m[i] = nm;
            o[i][0] *= corr; o[i][1] *= corr; o[i][2] *= corr; o[i][3] *= corr;
            *(float4*)&Ps[r0 + i][c0] = make_float4(s[i][0], s[i][1], s[i][2], s[i][3]);
        }
        __syncthreads();

#pragma unroll
        for (int j0 = 0; j0 < 64; j0 += 4) {
            float4 pv[4];
#pragma unroll
            for (int i = 0; i < 4; i++) pv[i] = *(const float4*)&Ps[r0 + i][j0];
#pragma unroll
            for (int t = 0; t < 4; t++) {
                float4 vv = *(const float4*)&Vs[j0 + t][c0];
#pragma unroll
                for (int i = 0; i < 4; i++) {
                    float pi = (t == 0) ? pv[i].x : (t == 1) ? pv[i].y
                             : (t == 2) ? pv[i].z : pv[i].w;
                    o[i][0] += pi * vv.x;
                    o[i][1] += pi * vv.y;
                    o[i][2] += pi * vv.z;
                    o[i][3] += pi * vv.w;
                }
            }
        }
    }

    long base3 = (long)b * SEQ * KP1 + h * DK;
#pragma unroll
    for (int i = 0; i < 4; i++) {
        float inv = 1.0f / l[i];
        float f0 = o[i][0] * inv, f1 = o[i][1] * inv;
        float f2 = o[i][2] * inv, f3 = o[i][3] * inv;
        __nv_bfloat16 h0, l0b, h1, l1b, h2, l2b, h3, l3b;
        split2(f0, h0, l0b); split2(f1, h1, l1b);
        split2(f2, h2, l2b); split2(f3, h3, l3b);
        __nv_bfloat16* op = out + base3 + (long)(q0 + r0 + i) * KP1 + c0;
        *(__nv_bfloat162*)(op) = mk2(h0, h1);
        *(__nv_bfloat162*)(op + 2) = mk2(h2, h3);
        *(__nv_bfloat162*)(op + DMODEL) = mk2(l0b, l1b);
        *(__nv_bfloat162*)(op + DMODEL + 2) = mk2(l2b, l3b);
        *(__nv_bfloat162*)(op + 2 * DMODEL) = mk2(h0, h1);
        *(__nv_bfloat162*)(op + 2 * DMODEL + 2) = mk2(h2, h3);
    }
}

// ---------------------------------------------------------------------------
extern "C" void kernel_launch(void* const* d_in, const int* in_sizes, int n_in,
                              void* d_out, int out_size) {
    const float* inputs   = (const float*)d_in[0];
    const float* mask     = (const float*)d_in[1];
    const float* rmsscale = (const float*)d_in[2];
    const float* Wq = (const float*)d_in[3];
    const float* bq = (const float*)d_in[4];
    const float* Wk = (const float*)d_in[5];
    const float* bk = (const float*)d_in[6];
    const float* Wv = (const float*)d_in[7];
    const float* bv = (const float*)d_in[8];
    const float* pds = (const float*)d_in[9];
    const float* Wpost = (const float*)d_in[10];
    const float* bpost = (const float*)d_in[11];
    const float* ln_scale = (const float*)d_in[12];
    const float* ln_bias  = (const float*)d_in[13];
    const float* W1 = (const float*)d_in[14];
    const float* b1 = (const float*)d_in[15];
    const float* W2 = (const float*)d_in[16];
    const float* b2 = (const float*)d_in[17];
    float* out = (float*)d_out;

    __nv_bfloat16 *xn_s, *attn_s, *y_s, *hid_s, *wq, *wk, *wv, *wpost, *w1, *w2;
    float *q, *k, *v, *h;
    cudaGetSymbolAddress((void**)&xn_s, g_xn_s);
    cudaGetSymbolAddress((void**)&q, g_q);
    cudaGetSymbolAddress((void**)&k, g_k);
    cudaGetSymbolAddress((void**)&v, g_v);
    cudaGetSymbolAddress((void**)&attn_s, g_attn_s);
    cudaGetSymbolAddress((void**)&h, g_h);
    cudaGetSymbolAddress((void**)&y_s, g_y_s);
    cudaGetSymbolAddress((void**)&hid_s, g_hid_s);
    cudaGetSymbolAddress((void**)&wq, g_wq);
    cudaGetSymbolAddress((void**)&wk, g_wk);
    cudaGetSymbolAddress((void**)&wv, g_wv);
    cudaGetSymbolAddress((void**)&wpost, g_wpost);
    cudaGetSymbolAddress((void**)&w1, g_w1);
    cudaGetSymbolAddress((void**)&w2, g_w2);

    const int SMEM = 65536;
    cudaFuncSetAttribute(gemm_mma<false, false, false>,
                         cudaFuncAttributeMaxDynamicSharedMemorySize, SMEM);
    cudaFuncSetAttribute(gemm_mma<false, true, false>,
                         cudaFuncAttributeMaxDynamicSharedMemorySize, SMEM);
    cudaFuncSetAttribute(gemm_mma<true, false, true>,
                         cudaFuncAttributeMaxDynamicSharedMemorySize, SMEM);

    // Weight splits (every call; weights may change between calls)
    split_w_kernel<<<1024, 256>>>(Wq, wq, DMODEL, (long)DMODEL * DMODEL / 4);
    split_w_kernel<<<1024, 256>>>(Wk, wk, DMODEL, (long)DMODEL * DMODEL / 4);
    split_w_kernel<<<1024, 256>>>(Wv, wv, DMODEL, (long)DMODEL * DMODEL / 4);
    split_w_kernel<<<1024, 256>>>(Wpost, wpost, DMODEL, (long)DMODEL * DMODEL / 4);
    split_w_kernel<<<4096, 256>>>(W1, w1, DMODEL, (long)HID * DMODEL / 4);
    split_w_kernel<<<4096, 256>>>(W2, w2, HID, (long)DMODEL * HID / 4);

    rmsnorm_split_kernel<<<MTOK, 256>>>(inputs, rmsscale, xn_s);

    dim3 g8(8, 64), g32(32, 64);
    gemm_mma<false, false, false><<<g8, 256, SMEM>>>(xn_s, wq, bq, nullptr, q, nullptr, DMODEL, KP1);
    gemm_mma<false, false, false><<<g8, 256, SMEM>>>(xn_s, wk, bk, nullptr, k, nullptr, DMODEL, KP1);
    gemm_mma<false, false, false><<<g8, 256, SMEM>>>(xn_s, wv, bv, nullptr, v, nullptr, DMODEL, KP1);

    attention_kernel<<<dim3(32, 64), 256>>>(q, k, v, mask, pds, attn_s);

    gemm_mma<false, true, false><<<g8, 256, SMEM>>>(attn_s, wpost, bpost, inputs, h, nullptr, DMODEL, KP1);
    layernorm_split_kernel<<<MTOK, 256>>>(h, ln_scale, ln_bias, y_s);
    gemm_mma<true, false, true><<<g32, 256, SMEM>>>(y_s, w1, b1, nullptr, nullptr, hid_s, HID, KP1);
    gemm_mma<false, true, false><<<g8, 256, SMEM>>>(hid_s, w2, b2, h, out, nullptr, DMODEL, KP2);
}

// round 5
// speedup vs baseline: 2.1271x; 2.1271x over previous
#include <cuda_runtime.h>
#include <cuda_bf16.h>
#include <cstdint>
#include <math.h>

#define MTOK 8192
#define DMODEL 1024
#define NH 16
#define DK 64
#define HID 4096
#define SEQ 2048
#define NQKV 3072
#define KP1 (3 * DMODEL)   /* 3072  */
#define KP2 (3 * HID)      /* 12288 */

// ---------------------------------------------------------------------------
// Scratch (__device__ globals; allocation is forbidden)
// ---------------------------------------------------------------------------
__device__ __nv_bfloat16 g_xn[MTOK * DMODEL];         // rmsnorm out (plain bf16)
__device__ __nv_bfloat16 g_qkv[(long)MTOK * NQKV];    // fused qkv out (q pre-scaled)
__device__ __nv_bfloat16 g_attn[MTOK * DMODEL];       // attention out (plain bf16)
__device__ float         g_h[MTOK * DMODEL];          // residual 1 (fp32)
__device__ __nv_bfloat16 g_y_s[MTOK * KP1];           // layernorm out, 3-term split
__device__ __nv_bfloat16 g_hid_s[(long)MTOK * KP2];   // relu(ffn1) out, 3-term split
__device__ __nv_bfloat16 g_wqkv[NQKV * DMODEL];       // concat(Wq,Wk,Wv) bf16
__device__ __nv_bfloat16 g_wpost[DMODEL * DMODEL];    // Wpost bf16
__device__ __nv_bfloat16 g_w1[HID * KP1];             // W1 split
__device__ __nv_bfloat16 g_w2[DMODEL * KP2];          // W2 split
__device__ float         g_bqkv[NQKV];                // concat bias
__device__ float         g_colscale[NQKV];            // pds scale for q cols, 1 else
__device__ int           g_mflags[(SEQ / 128) * (SEQ / 64)];

// ---------------------------------------------------------------------------
// Helpers
// ---------------------------------------------------------------------------
__device__ __forceinline__ uint32_t s2u(const void* p) {
    uint32_t a;
    asm("{ .reg .u64 t; cvta.to.shared.u64 t, %1; cvt.u32.u64 %0, t; }"
        : "=r"(a) : "l"(p));
    return a;
}
#define SW128(o) ((o) ^ (((o) >> 3) & 0x70))

__device__ __forceinline__ void split2(float f, __nv_bfloat16& h, __nv_bfloat16& l) {
    h = __float2bfloat16(f);
    l = __float2bfloat16(f - __bfloat162float(h));
}
__device__ __forceinline__ __nv_bfloat162 mk2(__nv_bfloat16 a, __nv_bfloat16 b) {
    __nv_bfloat162 r; r.x = a; r.y = b; return r;
}
__device__ __forceinline__ uint32_t packbf(float a, float b) {
    __nv_bfloat162 t = __floats2bfloat162_rn(a, b);
    return *(uint32_t*)&t;
}
__device__ __forceinline__ void cpa16(uint32_t dst, const void* src) {
    asm volatile("cp.async.cg.shared.global [%0], [%1], 16;"
                 :: "r"(dst), "l"(src) : "memory");
}
__device__ __forceinline__ void ldsm4(uint32_t* r, uint32_t addr) {
    asm volatile("ldmatrix.sync.aligned.m8n8.x4.shared.b16 {%0,%1,%2,%3}, [%4];"
                 : "=r"(r[0]), "=r"(r[1]), "=r"(r[2]), "=r"(r[3]) : "r"(addr));
}
__device__ __forceinline__ void ldsm4t(uint32_t* r, uint32_t addr) {
    asm volatile("ldmatrix.sync.aligned.m8n8.x4.trans.shared.b16 {%0,%1,%2,%3}, [%4];"
                 : "=r"(r[0]), "=r"(r[1]), "=r"(r[2]), "=r"(r[3]) : "r"(addr));
}
__device__ __forceinline__ void mma_bf16(float* c, const uint32_t* a,
                                         uint32_t b0, uint32_t b1) {
    asm volatile(
        "mma.sync.aligned.m16n8k16.row.col.f32.bf16.bf16.f32 "
        "{%0,%1,%2,%3}, {%4,%5,%6,%7}, {%8,%9}, {%0,%1,%2,%3};"
        : "+f"(c[0]), "+f"(c[1]), "+f"(c[2]), "+f"(c[3])
        : "r"(a[0]), "r"(a[1]), "r"(a[2]), "r"(a[3]), "r"(b0), "r"(b1));
}

// ---------------------------------------------------------------------------
// Prep kernels
// ---------------------------------------------------------------------------
// plain fp32 -> bf16 convert (vectorized)
__global__ __launch_bounds__(256) void conv_w_kernel(
    const float* __restrict__ W, __nv_bfloat16* __restrict__ dst, long n4) {
    long i = blockIdx.x * 256L + threadIdx.x;
    if (i >= n4) return;
    float4 v = ((const float4*)W)[i];
    ((__nv_bfloat162*)dst)[i * 2] = __floats2bfloat162_rn(v.x, v.y);
    ((__nv_bfloat162*)dst)[i * 2 + 1] = __floats2bfloat162_rn(v.z, v.w);
}

// Weight split: W fp32 [R,K] -> bf16 [R,3K] as [hi, hi, lo]
__global__ __launch_bounds__(256) void split_w_kernel(
    const float* __restrict__ W, __nv_bfloat16* __restrict__ out,
    int K, long total4) {
    long idx = blockIdx.x * 256L + threadIdx.x;
    if (idx >= total4) return;
    int kq = K >> 2;
    long m = idx / kq;
    int kk = (int)(idx % kq) << 2;
    float4 v = *(const float4*)(W + m * K + kk);
    __nv_bfloat16 h0, l0, h1, l1, h2, l2, h3, l3;
    split2(v.x, h0, l0); split2(v.y, h1, l1);
    split2(v.z, h2, l2); split2(v.w, h3, l3);
    __nv_bfloat16* o = out + m * (long)(3 * K) + kk;
    *(__nv_bfloat162*)(o) = mk2(h0, h1);
    *(__nv_bfloat162*)(o + 2) = mk2(h2, h3);
    *(__nv_bfloat162*)(o + K) = mk2(h0, h1);
    *(__nv_bfloat162*)(o + K + 2) = mk2(h2, h3);
    *(__nv_bfloat162*)(o + 2 * K) = mk2(l0, l1);
    *(__nv_bfloat162*)(o + 2 * K + 2) = mk2(l2, l3);
}

// concat biases + per-column scale for fused QKV
__global__ __launch_bounds__(256) void qkv_meta_kernel(
    const float* __restrict__ bq, const float* __restrict__ bk,
    const float* __restrict__ bv, const float* __restrict__ pds,
    float* __restrict__ bqkv, float* __restrict__ colscale) {
    int i = blockIdx.x * 256 + threadIdx.x;
    if (i >= NQKV) return;
    bqkv[i] = (i < 1024) ? bq[i] : (i < 2048) ? bk[i - 1024] : bv[i - 2048];
    colscale[i] = (i < 1024)
        ? 0.18033688f * log1pf(__expf(pds[i & 63]))
        : 1.0f;
}

// per-(128q x 64k)-tile mask nonzero flags
__global__ __launch_bounds__(256) void mask_flags_kernel(
    const float* __restrict__ mask, int* __restrict__ flags) {
    int qt = blockIdx.x >> 5, kt = blockIdx.x & 31;
    int nz = 0;
    for (int i = threadIdx.x; i < 128 * 64; i += 256) {
        int r = i >> 6, cc = i & 63;
        if (mask[(long)(qt * 128 + r) * SEQ + kt * 64 + cc] != 0.f) nz = 1;
    }
    nz = __syncthreads_or(nz);
    if (threadIdx.x == 0) flags[blockIdx.x] = nz;
}

// ---------------------------------------------------------------------------
// RMSNorm -> plain bf16 [M, DMODEL]
// ---------------------------------------------------------------------------
__global__ __launch_bounds__(256) void rmsnorm_kernel(
    const float* __restrict__ x, const float* __restrict__ scale,
    __nv_bfloat16* __restrict__ out) {
    int row = blockIdx.x;
    int tid = threadIdx.x;
    float4 v = ((const float4*)(x + (long)row * DMODEL))[tid];
    float ss = v.x * v.x + v.y * v.y + v.z * v.z + v.w * v.w;
#pragma unroll
    for (int w = 16; w; w >>= 1) ss += __shfl_xor_sync(0xffffffffu, ss, w);
    __shared__ float red[8];
    if ((tid & 31) == 0) red[tid >> 5] = ss;
    __syncthreads();
    float tot = 0.f;
#pragma unroll
    for (int i = 0; i < 8; i++) tot += red[i];
    float r = rsqrtf(tot * (1.0f / 1024.0f) + 1e-6f);
    float4 sc = ((const float4*)scale)[tid];
    __nv_bfloat16* o = out + (long)row * DMODEL + tid * 4;
    *(__nv_bfloat162*)(o) = __floats2bfloat162_rn(v.x * r * sc.x, v.y * r * sc.y);
    *(__nv_bfloat162*)(o + 2) = __floats2bfloat162_rn(v.z * r * sc.z, v.w * r * sc.w);
}

// ---------------------------------------------------------------------------
// LayerNorm -> split bf16 [M, 3K]
// ---------------------------------------------------------------------------
__global__ __launch_bounds__(256) void layernorm_split_kernel(
    const float* __restrict__ x, const float* __restrict__ scale,
    const float* __restrict__ bias, __nv_bfloat16* __restrict__ out) {
    int row = blockIdx.x;
    int tid = threadIdx.x;
    float4 v = ((const float4*)(x + (long)row * DMODEL))[tid];
    float s = v.x + v.y + v.z + v.w;
    float sq = v.x * v.x + v.y * v.y + v.z * v.z + v.w * v.w;
#pragma unroll
    for (int w = 16; w; w >>= 1) {
        s += __shfl_xor_sync(0xffffffffu, s, w);
        sq += __shfl_xor_sync(0xffffffffu, sq, w);
    }
    __shared__ float rs[8], rq[8];
    if ((tid & 31) == 0) { rs[tid >> 5] = s; rq[tid >> 5] = sq; }
    __syncthreads();
    float S = 0.f, Q = 0.f;
#pragma unroll
    for (int i = 0; i < 8; i++) { S += rs[i]; Q += rq[i]; }
    float mean = S * (1.0f / 1024.0f);
    float var = Q * (1.0f / 1024.0f) - mean * mean;
    float r = rsqrtf(var + 1e-6f);
    float4 sc = ((const float4*)scale)[tid];
    float4 bi = ((const float4*)bias)[tid];
    float f0 = (v.x - mean) * r * (1.0f + sc.x) + bi.x;
    float f1 = (v.y - mean) * r * (1.0f + sc.y) + bi.y;
    float f2 = (v.z - mean) * r * (1.0f + sc.z) + bi.z;
    float f3 = (v.w - mean) * r * (1.0f + sc.w) + bi.w;
    __nv_bfloat16 h0, l0, h1, l1, h2, l2, h3, l3;
    split2(f0, h0, l0); split2(f1, h1, l1);
    split2(f2, h2, l2); split2(f3, h3, l3);
    __nv_bfloat16* o = out + (long)row * KP1 + tid * 4;
    *(__nv_bfloat162*)(o) = mk2(h0, h1);
    *(__nv_bfloat162*)(o + 2) = mk2(h2, h3);
    *(__nv_bfloat162*)(o + DMODEL) = mk2(l0, l1);
    *(__nv_bfloat162*)(o + DMODEL + 2) = mk2(l2, l3);
    *(__nv_bfloat162*)(o + 2 * DMODEL) = mk2(h0, h1);
    *(__nv_bfloat162*)(o + 2 * DMODEL + 2) = mk2(h2, h3);
}

// ---------------------------------------------------------------------------
// mma.sync bf16 GEMM: C[m,n] = sum_k A[m,k]*B[n,k] + bias[n]
// EPI 0: fp32 out;  1: fp32 + res;  2: bf16 * colscale (qkv);  3: split+relu
// ---------------------------------------------------------------------------
template <int EPI>
__global__ void __launch_bounds__(256, 2) gemm_mma(
    const __nv_bfloat16* __restrict__ A, const __nv_bfloat16* __restrict__ Bw,
    const float* __restrict__ bias, const float* __restrict__ res,
    const float* __restrict__ colscale,
    float* __restrict__ Cf, __nv_bfloat16* __restrict__ Cs, int N, int Kp) {
    extern __shared__ char smem[];
    uint32_t sbase = s2u(smem);
    int tid = threadIdx.x;
    int wid = tid >> 5, lane = tid & 31;
    int wm = (wid & 1) * 64;
    int wn = (wid >> 1) * 32;
    long row0 = (long)blockIdx.y * 128, col0 = (long)blockIdx.x * 128;
    const __nv_bfloat16* Ab = A + row0 * (long)Kp;
    const __nv_bfloat16* Bb = Bw + col0 * (long)Kp;

    int ldr = tid >> 1;
    int ldc = (tid & 1) * 4;

    auto issue = [&](int c, int s) {
        long kc = (long)c << 6;
        uint32_t abase = sbase + (uint32_t)s * 32768u;
        uint32_t bbase = abase + 16384u;
        const __nv_bfloat16* ag = Ab + (long)ldr * Kp + kc + ldc * 8;
        const __nv_bfloat16* bg = Bb + (long)ldr * Kp + kc + ldc * 8;
#pragma unroll
        for (int i = 0; i < 4; i++) {
            uint32_t off = SW128((uint32_t)(ldr * 128 + (ldc + i) * 16));
            cpa16(abase + off, ag + i * 8);
            cpa16(bbase + off, bg + i * 8);
        }
        asm volatile("cp.async.commit_group;" ::: "memory");
    };

    float acc[4][4][4] = {};
    const int C = Kp >> 6;

    issue(0, 0);
    for (int c = 0; c < C; c++) {
        if (c + 1 < C) {
            issue(c + 1, (c + 1) & 1);
            asm volatile("cp.async.wait_group 1;" ::: "memory");
        } else {
            asm volatile("cp.async.wait_group 0;" ::: "memory");
        }
        __syncthreads();
        uint32_t abase = sbase + (uint32_t)(c & 1) * 32768u;
        uint32_t bbase = abase + 16384u;
#pragma unroll
        for (int ks = 0; ks < 4; ks++) {
            uint32_t a[4][4], b[2][4];
#pragma unroll
            for (int mt = 0; mt < 4; mt++) {
                int r = wm + mt * 16 + (lane & 15);
                uint32_t off = SW128((uint32_t)(r * 128 + ks * 32 + ((lane >> 4) << 4)));
                ldsm4(a[mt], abase + off);
            }
#pragma unroll
            for (int nt2 = 0; nt2 < 2; nt2++) {
                int nr = wn + nt2 * 16 + (lane & 7) + ((lane >> 4) << 3);
                uint32_t off = SW128(
                    (uint32_t)(nr * 128 + ks * 32 + (((lane >> 3) & 1) << 4)));
                ldsm4(b[nt2], bbase + off);
            }
#pragma unroll
            for (int mt = 0; mt < 4; mt++)
#pragma unroll
                for (int nt = 0; nt < 4; nt++)
                    mma_bf16(acc[mt][nt], a[mt],
                             b[nt >> 1][(nt & 1) * 2], b[nt >> 1][(nt & 1) * 2 + 1]);
        }
        __syncthreads();
    }

    int tq = lane >> 2, tr = lane & 3;
#pragma unroll
    for (int mt = 0; mt < 4; mt++) {
#pragma unroll
        for (int half = 0; half < 2; half++) {
            long row = row0 + wm + mt * 16 + tq + half * 8;
#pragma unroll
            for (int nt = 0; nt < 4; nt++) {
                int col = (int)col0 + wn + nt * 8 + tr * 2;
                float v0 = acc[mt][nt][half * 2 + 0] + bias[col];
                float v1 = acc[mt][nt][half * 2 + 1] + bias[col + 1];
                if (EPI == 3) { v0 = fmaxf(v0, 0.f); v1 = fmaxf(v1, 0.f); }
                if (EPI == 2) {
                    v0 *= colscale[col]; v1 *= colscale[col + 1];
                    *(__nv_bfloat162*)(Cs + row * (long)N + col) =
                        __floats2bfloat162_rn(v0, v1);
                } else if (EPI == 3) {
                    __nv_bfloat16 h0, l0, h1, l1;
                    split2(v0, h0, l0); split2(v1, h1, l1);
                    __nv_bfloat16* o = Cs + row * (long)(3 * N) + col;
                    *(__nv_bfloat162*)(o) = mk2(h0, h1);
                    *(__nv_bfloat162*)(o + N) = mk2(l0, l1);
                    *(__nv_bfloat162*)(o + 2 * N) = mk2(h0, h1);
                } else {
                    long idx = row * (long)N + col;
                    if (EPI == 1) {
                        float2 r2 = *(const float2*)(res + idx);
                        v0 += r2.x; v1 += r2.y;
                    }
                    float2 o2; o2.x = v0; o2.y = v1;
                    *(float2*)(Cf + idx) = o2;
                }
            }
        }
    }
}

// ---------------------------------------------------------------------------
// Flash attention, mma.sync bf16, 128q x 64k tiles, online fp32 softmax.
// qkv layout: [b*SEQ + s][3072]; q cols 0-1023 (pre-scaled), k +1024, v +2048.
// Each warp owns 16 full query rows (all 64 keys) -> softmax = 4-lane shuffles.
// ---------------------------------------------------------------------------
__global__ __launch_bounds__(256) void attn_mma_kernel(
    const __nv_bfloat16* __restrict__ qkv, const float* __restrict__ mask,
    const int* __restrict__ mflags, __nv_bfloat16* __restrict__ out) {
    extern __shared__ char smem[];
    uint32_t sb = s2u(smem);      // Q: 16KB; then 2 x (K 8KB + V 8KB)
    int tid = threadIdx.x, wid = tid >> 5, lane = tid & 31;
    int bh = blockIdx.y;
    int b = bh >> 4, h = bh & 15;
    int qt = blockIdx.x;
    int q0 = qt * 128;
    const __nv_bfloat16* base = qkv + (long)b * SEQ * NQKV + h * 64;

    // Q tile: 128 rows x 128B, cp.async group 0
    {
#pragma unroll
        for (int i = 0; i < 4; i++) {
            int idx = tid * 4 + i;
            int r = idx >> 3, ch = idx & 7;
            uint32_t off = SW128((uint32_t)(r * 128 + ch * 16));
            cpa16(sb + off, base + (long)(q0 + r) * NQKV + ch * 8);
        }
        asm volatile("cp.async.commit_group;" ::: "memory");
    }

    auto issue_kv = [&](int c, int s) {
        uint32_t kb = sb + 16384u + (uint32_t)s * 16384u;
        uint32_t vb = kb + 8192u;
        int k0 = c * 64;
#pragma unroll
        for (int i = 0; i < 2; i++) {
            int idx = tid * 2 + i;
            int r = idx >> 3, ch = idx & 7;
            uint32_t off = SW128((uint32_t)(r * 128 + ch * 16));
            const __nv_bfloat16* g = base + (long)(k0 + r) * NQKV + ch * 8;
            cpa16(kb + off, g + 1024);
            cpa16(vb + off, g + 2048);
        }
        asm volatile("cp.async.commit_group;" ::: "memory");
    };

    int wm = wid * 16;
    int tq = lane >> 2, tr = lane & 3;
    float m0 = -1e30f, m1 = -1e30f, l0 = 0.f, l1 = 0.f;
    float acc_o[8][4] = {};
    const int NT = SEQ / 64;   // 32

    issue_kv(0, 0);
    for (int c = 0; c < NT; c++) {
        if (c + 1 < NT) {
            issue_kv(c + 1, (c + 1) & 1);
            asm volatile("cp.async.wait_group 1;" ::: "memory");
        } else {
            asm volatile("cp.async.wait_group 0;" ::: "memory");
        }
        __syncthreads();
        uint32_t kb = sb + 16384u + (uint32_t)(c & 1) * 16384u;
        uint32_t vb = kb + 8192u;

        // ---- S = Q K^T : warp tile 16 x 64 (8 n-tiles of 8 keys) ----
        float sf[8][4] = {};
#pragma unroll
        for (int ks = 0; ks < 4; ks++) {
            uint32_t a[4];
            {
                int r = wm + (lane & 15);
                uint32_t off = SW128((uint32_t)(r * 128 + ks * 32 + ((lane >> 4) << 4)));
                ldsm4(a, sb + off);
            }
#pragma unroll
            for (int g = 0; g < 4; g++) {
                uint32_t bf[4];
                int nr = g * 16 + (lane & 7) + ((lane >> 4) << 3);
                uint32_t off = SW128(
                    (uint32_t)(nr * 128 + ks * 32 + (((lane >> 3) & 1) << 4)));
                ldsm4(bf, kb + off);
                mma_bf16(sf[2 * g], a, bf[0], bf[1]);
                mma_bf16(sf[2 * g + 1], a, bf[2], bf[3]);
            }
        }

        // ---- mask (skipped when tile is all-zero) ----
        if (mflags[qt * NT + c]) {
            int k0 = c * 64;
            long r0g = (long)(q0 + wm + tq) * SEQ + k0;
            long r1g = r0g + 8L * SEQ;
#pragma unroll
            for (int nt = 0; nt < 8; nt++) {
                int key = nt * 8 + tr * 2;
                float2 mk0 = *(const float2*)&mask[r0g + key];
                float2 mk1 = *(const float2*)&mask[r1g + key];
                sf[nt][0] += mk0.x; sf[nt][1] += mk0.y;
                sf[nt][2] += mk1.x; sf[nt][3] += mk1.y;
            }
        }

        // ---- online softmax (row halves: [0,1] row tq, [2,3] row tq+8) ----
        float tm0 = -1e30f, tm1 = -1e30f;
#pragma unroll
        for (int nt = 0; nt < 8; nt++) {
            tm0 = fmaxf(tm0, fmaxf(sf[nt][0], sf[nt][1]));
            tm1 = fmaxf(tm1, fmaxf(sf[nt][2], sf[nt][3]));
        }
#pragma unroll
        for (int w = 1; w <= 2; w <<= 1) {
            tm0 = fmaxf(tm0, __shfl_xor_sync(0xffffffffu, tm0, w));
            tm1 = fmaxf(tm1, __shfl_xor_sync(0xffffffffu, tm1, w));
        }
        float nm0 = fmaxf(m0, tm0), nm1 = fmaxf(m1, tm1);
        float corr0 = __expf(m0 - nm0), corr1 = __expf(m1 - nm1);
        m0 = nm0; m1 = nm1;
        float ts0 = 0.f, ts1 = 0.f;
#pragma unroll
        for (int nt = 0; nt < 8; nt++) {
            sf[nt][0] = __expf(sf[nt][0] - nm0);
            sf[nt][1] = __expf(sf[nt][1] - nm0);
            sf[nt][2] = __expf(sf[nt][2] - nm1);
            sf[nt][3] = __expf(sf[nt][3] - nm1);
            ts0 += sf[nt][0] + sf[nt][1];
            ts1 += sf[nt][2] + sf[nt][3];
        }
#pragma unroll
        for (int w = 1; w <= 2; w <<= 1) {
            ts0 += __shfl_xor_sync(0xffffffffu, ts0, w);
            ts1 += __shfl_xor_sync(0xffffffffu, ts1, w);
        }
        l0 = l0 * corr0 + ts0;
        l1 = l1 * corr1 + ts1;
#pragma unroll
        for (int nt = 0; nt < 8; nt++) {
            acc_o[nt][0] *= corr0; acc_o[nt][1] *= corr0;
            acc_o[nt][2] *= corr1; acc_o[nt][3] *= corr1;
        }

        // ---- O += P V : P frags straight from registers, V via ldmatrix.trans
#pragma unroll
        for (int kc = 0; kc < 4; kc++) {
            uint32_t pa[4];
            pa[0] = packbf(sf[2 * kc][0], sf[2 * kc][1]);
            pa[1] = packbf(sf[2 * kc][2], sf[2 * kc][3]);
            pa[2] = packbf(sf[2 * kc + 1][0], sf[2 * kc + 1][1]);
            pa[3] = packbf(sf[2 * kc + 1][2], sf[2 * kc + 1][3]);
#pragma unroll
            for (int nb = 0; nb < 4; nb++) {
                uint32_t bf[4];
                int r = kc * 16 + (lane & 15);
                uint32_t off = SW128(
                    (uint32_t)(r * 128 + nb * 32 + ((lane >> 4) << 4)));
                ldsm4t(bf, vb + off);
                mma_bf16(acc_o[2 * nb], pa, bf[0], bf[1]);
                mma_bf16(acc_o[2 * nb + 1], pa, bf[2], bf[3]);
            }
        }
        __syncthreads();
    }

    // ---- epilogue: normalize + write plain bf16 [token][DMODEL] ----
    float inv0 = 1.0f / l0, inv1 = 1.0f / l1;
    long t0 = (long)b * SEQ + q0 + wm + tq;
    __nv_bfloat16* o0 = out + t0 * DMODEL + h * 64;
    __nv_bfloat16* o1 = o0 + 8L * DMODEL;
#pragma unroll
    for (int nt = 0; nt < 8; nt++) {
        int col = nt * 8 + tr * 2;
        *(__nv_bfloat162*)(o0 + col) =
            __floats2bfloat162_rn(acc_o[nt][0] * inv0, acc_o[nt][1] * inv0);
        *(__nv_bfloat162*)(o1 + col) =
            __floats2bfloat162_rn(acc_o[nt][2] * inv1, acc_o[nt][3] * inv1);
    }
}

// ---------------------------------------------------------------------------
extern "C" void kernel_launch(void* const* d_in, const int* in_sizes, int n_in,
                              void* d_out, int out_size) {
    const float* inputs   = (const float*)d_in[0];
    const float* mask     = (const float*)d_in[1];
    const float* rmsscale = (const float*)d_in[2];
    const float* Wq = (const float*)d_in[3];
    const float* bq = (const float*)d_in[4];
    const float* Wk = (const float*)d_in[5];
    const float* bk = (const float*)d_in[6];
    const float* Wv = (const float*)d_in[7];
    const float* bv = (const float*)d_in[8];
    const float* pds = (const float*)d_in[9];
    const float* Wpost = (const float*)d_in[10];
    const float* bpost = (const float*)d_in[11];
    const float* ln_scale = (const float*)d_in[12];
    const float* ln_bias  = (const float*)d_in[13];
    const float* W1 = (const float*)d_in[14];
    const float* b1 = (const float*)d_in[15];
    const float* W2 = (const float*)d_in[16];
    const float* b2 = (const float*)d_in[17];
    float* out = (float*)d_out;

    __nv_bfloat16 *xn, *qkv, *attn, *y_s, *hid_s, *wqkv, *wpost, *w1, *w2;
    float *h, *bqkv, *colscale;
    int* mflags;
    cudaGetSymbolAddress((void**)&xn, g_xn);
    cudaGetSymbolAddress((void**)&qkv, g_qkv);
    cudaGetSymbolAddress((void**)&attn, g_attn);
    cudaGetSymbolAddress((void**)&h, g_h);
    cudaGetSymbolAddress((void**)&y_s, g_y_s);
    cudaGetSymbolAddress((void**)&hid_s, g_hid_s);
    cudaGetSymbolAddress((void**)&wqkv, g_wqkv);
    cudaGetSymbolAddress((void**)&wpost, g_wpost);
    cudaGetSymbolAddress((void**)&w1, g_w1);
    cudaGetSymbolAddress((void**)&w2, g_w2);
    cudaGetSymbolAddress((void**)&bqkv, g_bqkv);
    cudaGetSymbolAddress((void**)&colscale, g_colscale);
    cudaGetSymbolAddress((void**)&mflags, g_mflags);

    const int SMEM = 65536;
    cudaFuncSetAttribute(gemm_mma<1>, cudaFuncAttributeMaxDynamicSharedMemorySize, SMEM);
    cudaFuncSetAttribute(gemm_mma<2>, cudaFuncAttributeMaxDynamicSharedMemorySize, SMEM);
    cudaFuncSetAttribute(gemm_mma<3>, cudaFuncAttributeMaxDynamicSharedMemorySize, SMEM);
    const int ASMEM = 49152;
    cudaFuncSetAttribute(attn_mma_kernel, cudaFuncAttributeMaxDynamicSharedMemorySize, ASMEM);

    // weight prep
    conv_w_kernel<<<1024, 256>>>(Wq, wqkv, 262144);
    conv_w_kernel<<<1024, 256>>>(Wk, wqkv + 1024 * 1024, 262144);
    conv_w_kernel<<<1024, 256>>>(Wv, wqkv + 2048 * 1024, 262144);
    conv_w_kernel<<<1024, 256>>>(Wpost, wpost, 262144);
    split_w_kernel<<<4096, 256>>>(W1, w1, DMODEL, (long)HID * DMODEL / 4);
    split_w_kernel<<<4096, 256>>>(W2, w2, HID, (long)DMODEL * HID / 4);
    qkv_meta_kernel<<<12, 256>>>(bq, bk, bv, pds, bqkv, colscale);
    mask_flags_kernel<<<512, 256>>>(mask, mflags);

    rmsnorm_kernel<<<MTOK, 256>>>(inputs, rmsscale, xn);

    // fused QKV (bf16 out, q pre-scaled)
    gemm_mma<2><<<dim3(24, 64), 256, SMEM>>>(xn, wqkv, bqkv, nullptr, colscale,
                                             nullptr, qkv, NQKV, DMODEL);
    // attention
    attn_mma_kernel<<<dim3(16, 64), 256, ASMEM>>>(qkv, mask, mflags, attn);
    // post projection + residual
    gemm_mma<1><<<dim3(8, 64), 256, SMEM>>>(attn, wpost, bpost, inputs, nullptr,
                                            h, nullptr, DMODEL, DMODEL);
    layernorm_split_kernel<<<MTOK, 256>>>(h, ln_scale, ln_bias, y_s);
    // FFN (3-term split for precision)
    gemm_mma<3><<<dim3(32, 64), 256, SMEM>>>(y_s, w1, b1, nullptr, nullptr,
                                             nullptr, hid_s, HID, KP1);
    gemm_mma<1><<<dim3(8, 64), 256, SMEM>>>(hid_s, w2, b2, h, nullptr,
                                            out, nullptr, DMODEL, KP2);
}

// round 6
// speedup vs baseline: 3.9987x; 1.8799x over previous
#include <cuda_runtime.h>
#include <cuda_fp16.h>
#include <cstdint>
#include <math.h>

#define MTOK 8192
#define DMODEL 1024
#define NH 16
#define DK 64
#define HID 4096
#define SEQ 2048
#define NQKV 3072

// ---------------------------------------------------------------------------
// Scratch (__device__ globals; allocation is forbidden)
// ---------------------------------------------------------------------------
__device__ __half g_xn[MTOK * DMODEL];         // rmsnorm out
__device__ __half g_qkv[(long)MTOK * NQKV];    // fused qkv out (q pre-scaled)
__device__ __half g_attn[MTOK * DMODEL];       // attention out
__device__ float  g_h[MTOK * DMODEL];          // residual 1 (fp32)
__device__ __half g_y[MTOK * DMODEL];          // layernorm out
__device__ __half g_hid[(long)MTOK * HID];     // relu(ffn1) out
__device__ __half g_wqkv[NQKV * DMODEL];       // concat(Wq,Wk,Wv)
__device__ __half g_wpost[DMODEL * DMODEL];
__device__ __half g_w1[HID * DMODEL];
__device__ __half g_w2[DMODEL * HID];
__device__ float  g_bqkv[NQKV];
__device__ float  g_colscale[NQKV];
__device__ int    g_mflags[(SEQ / 128) * (SEQ / 64)];

// ---------------------------------------------------------------------------
// Helpers
// ---------------------------------------------------------------------------
__device__ __forceinline__ uint32_t s2u(const void* p) {
    uint32_t a;
    asm("{ .reg .u64 t; cvta.to.shared.u64 t, %1; cvt.u32.u64 %0, t; }"
        : "=r"(a) : "l"(p));
    return a;
}
#define SW128(o) ((o) ^ (((o) >> 3) & 0x70))

__device__ __forceinline__ uint32_t packh(float a, float b) {
    __half2 t = __floats2half2_rn(a, b);
    return *(uint32_t*)&t;
}
__device__ __forceinline__ void cpa16(uint32_t dst, const void* src) {
    asm volatile("cp.async.cg.shared.global [%0], [%1], 16;"
                 :: "r"(dst), "l"(src) : "memory");
}
__device__ __forceinline__ void ldsm4(uint32_t* r, uint32_t addr) {
    asm volatile("ldmatrix.sync.aligned.m8n8.x4.shared.b16 {%0,%1,%2,%3}, [%4];"
                 : "=r"(r[0]), "=r"(r[1]), "=r"(r[2]), "=r"(r[3]) : "r"(addr));
}
__device__ __forceinline__ void ldsm4t(uint32_t* r, uint32_t addr) {
    asm volatile("ldmatrix.sync.aligned.m8n8.x4.trans.shared.b16 {%0,%1,%2,%3}, [%4];"
                 : "=r"(r[0]), "=r"(r[1]), "=r"(r[2]), "=r"(r[3]) : "r"(addr));
}
__device__ __forceinline__ void mma_f16(float* c, const uint32_t* a,
                                        uint32_t b0, uint32_t b1) {
    asm volatile(
        "mma.sync.aligned.m16n8k16.row.col.f32.f16.f16.f32 "
        "{%0,%1,%2,%3}, {%4,%5,%6,%7}, {%8,%9}, {%0,%1,%2,%3};"
        : "+f"(c[0]), "+f"(c[1]), "+f"(c[2]), "+f"(c[3])
        : "r"(a[0]), "r"(a[1]), "r"(a[2]), "r"(a[3]), "r"(b0), "r"(b1));
}

// ---------------------------------------------------------------------------
// Prep kernels
// ---------------------------------------------------------------------------
__global__ __launch_bounds__(256) void conv_w_kernel(
    const float* __restrict__ W, __half* __restrict__ dst, long n4) {
    long i = blockIdx.x * 256L + threadIdx.x;
    if (i >= n4) return;
    float4 v = ((const float4*)W)[i];
    ((__half2*)dst)[i * 2] = __floats2half2_rn(v.x, v.y);
    ((__half2*)dst)[i * 2 + 1] = __floats2half2_rn(v.z, v.w);
}

__global__ __launch_bounds__(256) void qkv_meta_kernel(
    const float* __restrict__ bq, const float* __restrict__ bk,
    const float* __restrict__ bv, const float* __restrict__ pds,
    float* __restrict__ bqkv, float* __restrict__ colscale) {
    int i = blockIdx.x * 256 + threadIdx.x;
    if (i >= NQKV) return;
    bqkv[i] = (i < 1024) ? bq[i] : (i < 2048) ? bk[i - 1024] : bv[i - 2048];
    colscale[i] = (i < 1024)
        ? 0.18033688f * log1pf(__expf(pds[i & 63]))
        : 1.0f;
}

__global__ __launch_bounds__(256) void mask_flags_kernel(
    const float* __restrict__ mask, int* __restrict__ flags) {
    int qt = blockIdx.x >> 5, kt = blockIdx.x & 31;
    int nz = 0;
    for (int i = threadIdx.x; i < 128 * 64; i += 256) {
        int r = i >> 6, cc = i & 63;
        if (mask[(long)(qt * 128 + r) * SEQ + kt * 64 + cc] != 0.f) nz = 1;
    }
    nz = __syncthreads_or(nz);
    if (threadIdx.x == 0) flags[blockIdx.x] = nz;
}

// ---------------------------------------------------------------------------
// RMSNorm -> fp16 [M, DMODEL]
// ---------------------------------------------------------------------------
__global__ __launch_bounds__(256) void rmsnorm_kernel(
    const float* __restrict__ x, const float* __restrict__ scale,
    __half* __restrict__ out) {
    int row = blockIdx.x;
    int tid = threadIdx.x;
    float4 v = ((const float4*)(x + (long)row * DMODEL))[tid];
    float ss = v.x * v.x + v.y * v.y + v.z * v.z + v.w * v.w;
#pragma unroll
    for (int w = 16; w; w >>= 1) ss += __shfl_xor_sync(0xffffffffu, ss, w);
    __shared__ float red[8];
    if ((tid & 31) == 0) red[tid >> 5] = ss;
    __syncthreads();
    float tot = 0.f;
#pragma unroll
    for (int i = 0; i < 8; i++) tot += red[i];
    float r = rsqrtf(tot * (1.0f / 1024.0f) + 1e-6f);
    float4 sc = ((const float4*)scale)[tid];
    __half* o = out + (long)row * DMODEL + tid * 4;
    *(__half2*)(o) = __floats2half2_rn(v.x * r * sc.x, v.y * r * sc.y);
    *(__half2*)(o + 2) = __floats2half2_rn(v.z * r * sc.z, v.w * r * sc.w);
}

// ---------------------------------------------------------------------------
// LayerNorm -> fp16 [M, DMODEL]
// ---------------------------------------------------------------------------
__global__ __launch_bounds__(256) void layernorm_kernel(
    const float* __restrict__ x, const float* __restrict__ scale,
    const float* __restrict__ bias, __half* __restrict__ out) {
    int row = blockIdx.x;
    int tid = threadIdx.x;
    float4 v = ((const float4*)(x + (long)row * DMODEL))[tid];
    float s = v.x + v.y + v.z + v.w;
    float sq = v.x * v.x + v.y * v.y + v.z * v.z + v.w * v.w;
#pragma unroll
    for (int w = 16; w; w >>= 1) {
        s += __shfl_xor_sync(0xffffffffu, s, w);
        sq += __shfl_xor_sync(0xffffffffu, sq, w);
    }
    __shared__ float rs[8], rq[8];
    if ((tid & 31) == 0) { rs[tid >> 5] = s; rq[tid >> 5] = sq; }
    __syncthreads();
    float S = 0.f, Q = 0.f;
#pragma unroll
    for (int i = 0; i < 8; i++) { S += rs[i]; Q += rq[i]; }
    float mean = S * (1.0f / 1024.0f);
    float var = Q * (1.0f / 1024.0f) - mean * mean;
    float r = rsqrtf(var + 1e-6f);
    float4 sc = ((const float4*)scale)[tid];
    float4 bi = ((const float4*)bias)[tid];
    __half* o = out + (long)row * DMODEL + tid * 4;
    *(__half2*)(o) = __floats2half2_rn(
        (v.x - mean) * r * (1.0f + sc.x) + bi.x,
        (v.y - mean) * r * (1.0f + sc.y) + bi.y);
    *(__half2*)(o + 2) = __floats2half2_rn(
        (v.z - mean) * r * (1.0f + sc.z) + bi.z,
        (v.w - mean) * r * (1.0f + sc.w) + bi.w);
}

// ---------------------------------------------------------------------------
// mma.sync fp16 GEMM: C[m,n] = sum_k A[m,k]*B[n,k] + bias[n]
// EPI 1: fp32 + res;  2: f16 * colscale (qkv);  3: f16 + relu
// ---------------------------------------------------------------------------
template <int EPI>
__global__ void __launch_bounds__(256, 2) gemm_mma(
    const __half* __restrict__ A, const __half* __restrict__ Bw,
    const float* __restrict__ bias, const float* __restrict__ res,
    const float* __restrict__ colscale,
    float* __restrict__ Cf, __half* __restrict__ Cs, int N, int Kp) {
    extern __shared__ char smem[];
    uint32_t sbase = s2u(smem);
    int tid = threadIdx.x;
    int wid = tid >> 5, lane = tid & 31;
    int wm = (wid & 1) * 64;
    int wn = (wid >> 1) * 32;
    long row0 = (long)blockIdx.y * 128, col0 = (long)blockIdx.x * 128;
    const __half* Ab = A + row0 * (long)Kp;
    const __half* Bb = Bw + col0 * (long)Kp;

    int ldr = tid >> 1;
    int ldc = (tid & 1) * 4;

    auto issue = [&](int c, int s) {
        long kc = (long)c << 6;
        uint32_t abase = sbase + (uint32_t)s * 32768u;
        uint32_t bbase = abase + 16384u;
        const __half* ag = Ab + (long)ldr * Kp + kc + ldc * 8;
        const __half* bg = Bb + (long)ldr * Kp + kc + ldc * 8;
#pragma unroll
        for (int i = 0; i < 4; i++) {
            uint32_t off = SW128((uint32_t)(ldr * 128 + (ldc + i) * 16));
            cpa16(abase + off, ag + i * 8);
            cpa16(bbase + off, bg + i * 8);
        }
        asm volatile("cp.async.commit_group;" ::: "memory");
    };

    float acc[4][4][4] = {};
    const int C = Kp >> 6;

    issue(0, 0);
    for (int c = 0; c < C; c++) {
        if (c + 1 < C) {
            issue(c + 1, (c + 1) & 1);
            asm volatile("cp.async.wait_group 1;" ::: "memory");
        } else {
            asm volatile("cp.async.wait_group 0;" ::: "memory");
        }
        __syncthreads();
        uint32_t abase = sbase + (uint32_t)(c & 1) * 32768u;
        uint32_t bbase = abase + 16384u;
#pragma unroll
        for (int ks = 0; ks < 4; ks++) {
            uint32_t a[4][4], b[2][4];
#pragma unroll
            for (int mt = 0; mt < 4; mt++) {
                int r = wm + mt * 16 + (lane & 15);
                uint32_t off = SW128((uint32_t)(r * 128 + ks * 32 + ((lane >> 4) << 4)));
                ldsm4(a[mt], abase + off);
            }
#pragma unroll
            for (int nt2 = 0; nt2 < 2; nt2++) {
                int nr = wn + nt2 * 16 + (lane & 7) + ((lane >> 4) << 3);
                uint32_t off = SW128(
                    (uint32_t)(nr * 128 + ks * 32 + (((lane >> 3) & 1) << 4)));
                ldsm4(b[nt2], bbase + off);
            }
#pragma unroll
            for (int mt = 0; mt < 4; mt++)
#pragma unroll
                for (int nt = 0; nt < 4; nt++)
                    mma_f16(acc[mt][nt], a[mt],
                            b[nt >> 1][(nt & 1) * 2], b[nt >> 1][(nt & 1) * 2 + 1]);
        }
        __syncthreads();
    }

    int tq = lane >> 2, tr = lane & 3;
#pragma unroll
    for (int mt = 0; mt < 4; mt++) {
#pragma unroll
        for (int half = 0; half < 2; half++) {
            long row = row0 + wm + mt * 16 + tq + half * 8;
#pragma unroll
            for (int nt = 0; nt < 4; nt++) {
                int col = (int)col0 + wn + nt * 8 + tr * 2;
                float v0 = acc[mt][nt][half * 2 + 0] + bias[col];
                float v1 = acc[mt][nt][half * 2 + 1] + bias[col + 1];
                if (EPI == 2) {
                    v0 *= colscale[col]; v1 *= colscale[col + 1];
                    *(__half2*)(Cs + row * (long)N + col) =
                        __floats2half2_rn(v0, v1);
                } else if (EPI == 3) {
                    v0 = fmaxf(v0, 0.f); v1 = fmaxf(v1, 0.f);
                    *(__half2*)(Cs + row * (long)N + col) =
                        __floats2half2_rn(v0, v1);
                } else {
                    long idx = row * (long)N + col;
                    float2 r2 = *(const float2*)(res + idx);
                    v0 += r2.x; v1 += r2.y;
                    float2 o2; o2.x = v0; o2.y = v1;
                    *(float2*)(Cf + idx) = o2;
                }
            }
        }
    }
}

// ---------------------------------------------------------------------------
// Flash attention, mma.sync fp16, 128q x 64k tiles, online fp32 softmax.
// qkv layout: [b*SEQ + s][3072]; q cols 0-1023 (pre-scaled), k +1024, v +2048.
// ---------------------------------------------------------------------------
__global__ __launch_bounds__(256) void attn_mma_kernel(
    const __half* __restrict__ qkv, const float* __restrict__ mask,
    const int* __restrict__ mflags, __half* __restrict__ out) {
    extern __shared__ char smem[];
    uint32_t sb = s2u(smem);      // Q: 16KB; then 2 x (K 8KB + V 8KB)
    int tid = threadIdx.x, wid = tid >> 5, lane = tid & 31;
    int bh = blockIdx.y;
    int b = bh >> 4, h = bh & 15;
    int qt = blockIdx.x;
    int q0 = qt * 128;
    const __half* base = qkv + (long)b * SEQ * NQKV + h * 64;

    {
#pragma unroll
        for (int i = 0; i < 4; i++) {
            int idx = tid * 4 + i;
            int r = idx >> 3, ch = idx & 7;
            uint32_t off = SW128((uint32_t)(r * 128 + ch * 16));
            cpa16(sb + off, base + (long)(q0 + r) * NQKV + ch * 8);
        }
        asm volatile("cp.async.commit_group;" ::: "memory");
    }

    auto issue_kv = [&](int c, int s) {
        uint32_t kb = sb + 16384u + (uint32_t)s * 16384u;
        uint32_t vb = kb + 8192u;
        int k0 = c * 64;
#pragma unroll
        for (int i = 0; i < 2; i++) {
            int idx = tid * 2 + i;
            int r = idx >> 3, ch = idx & 7;
            uint32_t off = SW128((uint32_t)(r * 128 + ch * 16));
            const __half* g = base + (long)(k0 + r) * NQKV + ch * 8;
            cpa16(kb + off, g + 1024);
            cpa16(vb + off, g + 2048);
        }
        asm volatile("cp.async.commit_group;" ::: "memory");
    };

    int wm = wid * 16;
    int tq = lane >> 2, tr = lane & 3;
    float m0 = -1e30f, m1 = -1e30f, l0 = 0.f, l1 = 0.f;
    float acc_o[8][4] = {};
    const int NT = SEQ / 64;   // 32

    issue_kv(0, 0);
    for (int c = 0; c < NT; c++) {
        if (c + 1 < NT) {
            issue_kv(c + 1, (c + 1) & 1);
            asm volatile("cp.async.wait_group 1;" ::: "memory");
        } else {
            asm volatile("cp.async.wait_group 0;" ::: "memory");
        }
        __syncthreads();
        uint32_t kb = sb + 16384u + (uint32_t)(c & 1) * 16384u;
        uint32_t vb = kb + 8192u;

        // ---- S = Q K^T ----
        float sf[8][4] = {};
#pragma unroll
        for (int ks = 0; ks < 4; ks++) {
            uint32_t a[4];
            {
                int r = wm + (lane & 15);
                uint32_t off = SW128((uint32_t)(r * 128 + ks * 32 + ((lane >> 4) << 4)));
                ldsm4(a, sb + off);
            }
#pragma unroll
            for (int g = 0; g < 4; g++) {
                uint32_t bf[4];
                int nr = g * 16 + (lane & 7) + ((lane >> 4) << 3);
                uint32_t off = SW128(
                    (uint32_t)(nr * 128 + ks * 32 + (((lane >> 3) & 1) << 4)));
                ldsm4(bf, kb + off);
                mma_f16(sf[2 * g], a, bf[0], bf[1]);
                mma_f16(sf[2 * g + 1], a, bf[2], bf[3]);
            }
        }

        // ---- mask (skipped when tile is all-zero) ----
        if (mflags[qt * NT + c]) {
            int k0 = c * 64;
            long r0g = (long)(q0 + wm + tq) * SEQ + k0;
            long r1g = r0g + 8L * SEQ;
#pragma unroll
            for (int nt = 0; nt < 8; nt++) {
                int key = nt * 8 + tr * 2;
                float2 mk0 = *(const float2*)&mask[r0g + key];
                float2 mk1 = *(const float2*)&mask[r1g + key];
                sf[nt][0] += mk0.x; sf[nt][1] += mk0.y;
                sf[nt][2] += mk1.x; sf[nt][3] += mk1.y;
            }
        }

        // ---- online softmax ----
        float tm0 = -1e30f, tm1 = -1e30f;
#pragma unroll
        for (int nt = 0; nt < 8; nt++) {
            tm0 = fmaxf(tm0, fmaxf(sf[nt][0], sf[nt][1]));
            tm1 = fmaxf(tm1, fmaxf(sf[nt][2], sf[nt][3]));
        }
#pragma unroll
        for (int w = 1; w <= 2; w <<= 1) {
            tm0 = fmaxf(tm0, __shfl_xor_sync(0xffffffffu, tm0, w));
            tm1 = fmaxf(tm1, __shfl_xor_sync(0xffffffffu, tm1, w));
        }
        float nm0 = fmaxf(m0, tm0), nm1 = fmaxf(m1, tm1);
        float corr0 = __expf(m0 - nm0), corr1 = __expf(m1 - nm1);
        m0 = nm0; m1 = nm1;
        float ts0 = 0.f, ts1 = 0.f;
#pragma unroll
        for (int nt = 0; nt < 8; nt++) {
            sf[nt][0] = __expf(sf[nt][0] - nm0);
            sf[nt][1] = __expf(sf[nt][1] - nm0);
            sf[nt][2] = __expf(sf[nt][2] - nm1);
            sf[nt][3] = __expf(sf[nt][3] - nm1);
            ts0 += sf[nt][0] + sf[nt][1];
            ts1 += sf[nt][2] + sf[nt][3];
        }
#pragma unroll
        for (int w = 1; w <= 2; w <<= 1) {
            ts0 += __shfl_xor_sync(0xffffffffu, ts0, w);
            ts1 += __shfl_xor_sync(0xffffffffu, ts1, w);
        }
        l0 = l0 * corr0 + ts0;
        l1 = l1 * corr1 + ts1;
#pragma unroll
        for (int nt = 0; nt < 8; nt++) {
            acc_o[nt][0] *= corr0; acc_o[nt][1] *= corr0;
            acc_o[nt][2] *= corr1; acc_o[nt][3] *= corr1;
        }

        // ---- O += P V ----
#pragma unroll
        for (int kc = 0; kc < 4; kc++) {
            uint32_t pa[4];
            pa[0] = packh(sf[2 * kc][0], sf[2 * kc][1]);
            pa[1] = packh(sf[2 * kc][2], sf[2 * kc][3]);
            pa[2] = packh(sf[2 * kc + 1][0], sf[2 * kc + 1][1]);
            pa[3] = packh(sf[2 * kc + 1][2], sf[2 * kc + 1][3]);
#pragma unroll
            for (int nb = 0; nb < 4; nb++) {
                uint32_t bf[4];
                int r = kc * 16 + (lane & 15);
                uint32_t off = SW128(
                    (uint32_t)(r * 128 + nb * 32 + ((lane >> 4) << 4)));
                ldsm4t(bf, vb + off);
                mma_f16(acc_o[2 * nb], pa, bf[0], bf[1]);
                mma_f16(acc_o[2 * nb + 1], pa, bf[2], bf[3]);
            }
        }
        __syncthreads();
    }

    float inv0 = 1.0f / l0, inv1 = 1.0f / l1;
    long t0 = (long)b * SEQ + q0 + wm + tq;
    __half* o0 = out + t0 * DMODEL + h * 64;
    __half* o1 = o0 + 8L * DMODEL;
#pragma unroll
    for (int nt = 0; nt < 8; nt++) {
        int col = nt * 8 + tr * 2;
        *(__half2*)(o0 + col) =
            __floats2half2_rn(acc_o[nt][0] * inv0, acc_o[nt][1] * inv0);
        *(__half2*)(o1 + col) =
            __floats2half2_rn(acc_o[nt][2] * inv1, acc_o[nt][3] * inv1);
    }
}

// ---------------------------------------------------------------------------
extern "C" void kernel_launch(void* const* d_in, const int* in_sizes, int n_in,
                              void* d_out, int out_size) {
    const float* inputs   = (const float*)d_in[0];
    const float* mask     = (const float*)d_in[1];
    const float* rmsscale = (const float*)d_in[2];
    const float* Wq = (const float*)d_in[3];
    const float* bq = (const float*)d_in[4];
    const float* Wk = (const float*)d_in[5];
    const float* bk = (const float*)d_in[6];
    const float* Wv = (const float*)d_in[7];
    const float* bv = (const float*)d_in[8];
    const float* pds = (const float*)d_in[9];
    const float* Wpost = (const float*)d_in[10];
    const float* bpost = (const float*)d_in[11];
    const float* ln_scale = (const float*)d_in[12];
    const float* ln_bias  = (const float*)d_in[13];
    const float* W1 = (const float*)d_in[14];
    const float* b1 = (const float*)d_in[15];
    const float* W2 = (const float*)d_in[16];
    const float* b2 = (const float*)d_in[17];
    float* out = (float*)d_out;

    __half *xn, *qkv, *attn, *y, *hid, *wqkv, *wpost, *w1, *w2;
    float *h, *bqkv, *colscale;
    int* mflags;
    cudaGetSymbolAddress((void**)&xn, g_xn);
    cudaGetSymbolAddress((void**)&qkv, g_qkv);
    cudaGetSymbolAddress((void**)&attn, g_attn);
    cudaGetSymbolAddress((void**)&h, g_h);
    cudaGetSymbolAddress((void**)&y, g_y);
    cudaGetSymbolAddress((void**)&hid, g_hid);
    cudaGetSymbolAddress((void**)&wqkv, g_wqkv);
    cudaGetSymbolAddress((void**)&wpost, g_wpost);
    cudaGetSymbolAddress((void**)&w1, g_w1);
    cudaGetSymbolAddress((void**)&w2, g_w2);
    cudaGetSymbolAddress((void**)&bqkv, g_bqkv);
    cudaGetSymbolAddress((void**)&colscale, g_colscale);
    cudaGetSymbolAddress((void**)&mflags, g_mflags);

    const int SMEM = 65536;
    cudaFuncSetAttribute(gemm_mma<1>, cudaFuncAttributeMaxDynamicSharedMemorySize, SMEM);
    cudaFuncSetAttribute(gemm_mma<2>, cudaFuncAttributeMaxDynamicSharedMemorySize, SMEM);
    cudaFuncSetAttribute(gemm_mma<3>, cudaFuncAttributeMaxDynamicSharedMemorySize, SMEM);
    const int ASMEM = 49152;
    cudaFuncSetAttribute(attn_mma_kernel, cudaFuncAttributeMaxDynamicSharedMemorySize, ASMEM);

    // weight prep (fp32 -> fp16)
    conv_w_kernel<<<1024, 256>>>(Wq, wqkv, 262144);
    conv_w_kernel<<<1024, 256>>>(Wk, wqkv + 1024 * 1024, 262144);
    conv_w_kernel<<<1024, 256>>>(Wv, wqkv + 2048 * 1024, 262144);
    conv_w_kernel<<<1024, 256>>>(Wpost, wpost, 262144);
    conv_w_kernel<<<4096, 256>>>(W1, w1, 1048576);
    conv_w_kernel<<<4096, 256>>>(W2, w2, 1048576);
    qkv_meta_kernel<<<12, 256>>>(bq, bk, bv, pds, bqkv, colscale);
    mask_flags_kernel<<<512, 256>>>(mask, mflags);

    rmsnorm_kernel<<<MTOK, 256>>>(inputs, rmsscale, xn);

    // fused QKV (f16 out, q pre-scaled)
    gemm_mma<2><<<dim3(24, 64), 256, SMEM>>>(xn, wqkv, bqkv, nullptr, colscale,
                                             nullptr, qkv, NQKV, DMODEL);
    // attention
    attn_mma_kernel<<<dim3(16, 64), 256, ASMEM>>>(qkv, mask, mflags, attn);
    // post projection + residual
    gemm_mma<1><<<dim3(8, 64), 256, SMEM>>>(attn, wpost, bpost, inputs, nullptr,
                                            h, nullptr, DMODEL, DMODEL);
    layernorm_kernel<<<MTOK, 256>>>(h, ln_scale, ln_bias, y);
    // FFN single-pass fp16
    gemm_mma<3><<<dim3(32, 64), 256, SMEM>>>(y, w1, b1, nullptr, nullptr,
                                             nullptr, hid, HID, DMODEL);
    gemm_mma<1><<<dim3(8, 64), 256, SMEM>>>(hid, w2, b2, h, nullptr,
                                            out, nullptr, DMODEL, HID);
}

// round 7
// speedup vs baseline: 4.3046x; 1.0765x over previous
#include <cuda_runtime.h>
#include <cuda_fp16.h>
#include <cstdint>
#include <math.h>

#define MTOK 8192
#define DMODEL 1024
#define NH 16
#define DK 64
#define HID 4096
#define SEQ 2048
#define NQKV 3072

// ---------------------------------------------------------------------------
// Scratch (__device__ globals; allocation is forbidden)
// ---------------------------------------------------------------------------
__device__ __half g_xn[MTOK * DMODEL];         // rmsnorm out
__device__ __half g_qkv[(long)MTOK * NQKV];    // fused qkv out (q pre-scaled)
__device__ __half g_attn[MTOK * DMODEL];       // attention out
__device__ float  g_h[MTOK * DMODEL];          // residual 1 (fp32)
__device__ __half g_y[MTOK * DMODEL];          // layernorm out
__device__ __half g_hid[(long)MTOK * HID];     // relu(ffn1) out
__device__ __half g_wqkv[NQKV * DMODEL];       // concat(Wq,Wk,Wv)
__device__ __half g_wpost[DMODEL * DMODEL];
__device__ __half g_w1[HID * DMODEL];
__device__ __half g_w2[DMODEL * HID];
__device__ float  g_bqkv[NQKV];
__device__ float  g_colscale[NQKV];
__device__ int    g_mflags[(SEQ / 128) * (SEQ / 64)];

// ---------------------------------------------------------------------------
// Helpers
// ---------------------------------------------------------------------------
__device__ __forceinline__ uint32_t s2u(const void* p) {
    uint32_t a;
    asm("{ .reg .u64 t; cvta.to.shared.u64 t, %1; cvt.u32.u64 %0, t; }"
        : "=r"(a) : "l"(p));
    return a;
}
#define SW128(o) ((o) ^ (((o) >> 3) & 0x70))

__device__ __forceinline__ uint32_t packh(float a, float b) {
    __half2 t = __floats2half2_rn(a, b);
    return *(uint32_t*)&t;
}
__device__ __forceinline__ void cpa16(uint32_t dst, const void* src) {
    asm volatile("cp.async.cg.shared.global [%0], [%1], 16;"
                 :: "r"(dst), "l"(src) : "memory");
}
__device__ __forceinline__ void cpcommit() {
    asm volatile("cp.async.commit_group;" ::: "memory");
}
__device__ __forceinline__ void ldsm4(uint32_t* r, uint32_t addr) {
    asm volatile("ldmatrix.sync.aligned.m8n8.x4.shared.b16 {%0,%1,%2,%3}, [%4];"
                 : "=r"(r[0]), "=r"(r[1]), "=r"(r[2]), "=r"(r[3]) : "r"(addr));
}
__device__ __forceinline__ void ldsm4t(uint32_t* r, uint32_t addr) {
    asm volatile("ldmatrix.sync.aligned.m8n8.x4.trans.shared.b16 {%0,%1,%2,%3}, [%4];"
                 : "=r"(r[0]), "=r"(r[1]), "=r"(r[2]), "=r"(r[3]) : "r"(addr));
}
__device__ __forceinline__ void mma_f16(float* c, const uint32_t* a,
                                        uint32_t b0, uint32_t b1) {
    asm volatile(
        "mma.sync.aligned.m16n8k16.row.col.f32.f16.f16.f32 "
        "{%0,%1,%2,%3}, {%4,%5,%6,%7}, {%8,%9}, {%0,%1,%2,%3};"
        : "+f"(c[0]), "+f"(c[1]), "+f"(c[2]), "+f"(c[3])
        : "r"(a[0]), "r"(a[1]), "r"(a[2]), "r"(a[3]), "r"(b0), "r"(b1));
}

// ---------------------------------------------------------------------------
// Prep: convert all 6 weight matrices fp32->fp16 in one launch
// float4 units: Wq/Wk/Wv/Wpost 262144 each, W1/W2 1048576 each = 3145728
// ---------------------------------------------------------------------------
__global__ __launch_bounds__(256) void conv_all_kernel(
    const float* __restrict__ Wq, const float* __restrict__ Wk,
    const float* __restrict__ Wv, const float* __restrict__ Wpost,
    const float* __restrict__ W1, const float* __restrict__ W2,
    __half* __restrict__ wqkv, __half* __restrict__ wpost,
    __half* __restrict__ w1, __half* __restrict__ w2) {
    long i = blockIdx.x * 256L + threadIdx.x;
    const float* src;
    __half* dst;
    long off;
    if (i < 262144) { src = Wq; dst = wqkv; off = i; }
    else if (i < 524288) { src = Wk; dst = wqkv + 1048576; off = i - 262144; }
    else if (i < 786432) { src = Wv; dst = wqkv + 2097152; off = i - 524288; }
    else if (i < 1048576) { src = Wpost; dst = wpost; off = i - 786432; }
    else if (i < 2097152) { src = W1; dst = w1; off = i - 1048576; }
    else { src = W2; dst = w2; off = i - 2097152; }
    float4 v = ((const float4*)src)[off];
    ((__half2*)dst)[off * 2] = __floats2half2_rn(v.x, v.y);
    ((__half2*)dst)[off * 2 + 1] = __floats2half2_rn(v.z, v.w);
}

__global__ __launch_bounds__(256) void qkv_meta_kernel(
    const float* __restrict__ bq, const float* __restrict__ bk,
    const float* __restrict__ bv, const float* __restrict__ pds,
    float* __restrict__ bqkv, float* __restrict__ colscale) {
    int i = blockIdx.x * 256 + threadIdx.x;
    if (i >= NQKV) return;
    bqkv[i] = (i < 1024) ? bq[i] : (i < 2048) ? bk[i - 1024] : bv[i - 2048];
    colscale[i] = (i < 1024)
        ? 0.18033688f * log1pf(__expf(pds[i & 63]))
        : 1.0f;
}

__global__ __launch_bounds__(256) void mask_flags_kernel(
    const float* __restrict__ mask, int* __restrict__ flags) {
    int qt = blockIdx.x >> 5, kt = blockIdx.x & 31;
    int nz = 0;
    for (int i = threadIdx.x; i < 128 * 64; i += 256) {
        int r = i >> 6, cc = i & 63;
        if (mask[(long)(qt * 128 + r) * SEQ + kt * 64 + cc] != 0.f) nz = 1;
    }
    nz = __syncthreads_or(nz);
    if (threadIdx.x == 0) flags[blockIdx.x] = nz;
}

// ---------------------------------------------------------------------------
// RMSNorm -> fp16 [M, DMODEL]
// ---------------------------------------------------------------------------
__global__ __launch_bounds__(256) void rmsnorm_kernel(
    const float* __restrict__ x, const float* __restrict__ scale,
    __half* __restrict__ out) {
    int row = blockIdx.x;
    int tid = threadIdx.x;
    float4 v = ((const float4*)(x + (long)row * DMODEL))[tid];
    float ss = v.x * v.x + v.y * v.y + v.z * v.z + v.w * v.w;
#pragma unroll
    for (int w = 16; w; w >>= 1) ss += __shfl_xor_sync(0xffffffffu, ss, w);
    __shared__ float red[8];
    if ((tid & 31) == 0) red[tid >> 5] = ss;
    __syncthreads();
    float tot = 0.f;
#pragma unroll
    for (int i = 0; i < 8; i++) tot += red[i];
    float r = rsqrtf(tot * (1.0f / 1024.0f) + 1e-6f);
    float4 sc = ((const float4*)scale)[tid];
    __half* o = out + (long)row * DMODEL + tid * 4;
    *(__half2*)(o) = __floats2half2_rn(v.x * r * sc.x, v.y * r * sc.y);
    *(__half2*)(o + 2) = __floats2half2_rn(v.z * r * sc.z, v.w * r * sc.w);
}

// ---------------------------------------------------------------------------
// LayerNorm -> fp16 [M, DMODEL]
// ---------------------------------------------------------------------------
__global__ __launch_bounds__(256) void layernorm_kernel(
    const float* __restrict__ x, const float* __restrict__ scale,
    const float* __restrict__ bias, __half* __restrict__ out) {
    int row = blockIdx.x;
    int tid = threadIdx.x;
    float4 v = ((const float4*)(x + (long)row * DMODEL))[tid];
    float s = v.x + v.y + v.z + v.w;
    float sq = v.x * v.x + v.y * v.y + v.z * v.z + v.w * v.w;
#pragma unroll
    for (int w = 16; w; w >>= 1) {
        s += __shfl_xor_sync(0xffffffffu, s, w);
        sq += __shfl_xor_sync(0xffffffffu, sq, w);
    }
    __shared__ float rs[8], rq[8];
    if ((tid & 31) == 0) { rs[tid >> 5] = s; rq[tid >> 5] = sq; }
    __syncthreads();
    float S = 0.f, Q = 0.f;
#pragma unroll
    for (int i = 0; i < 8; i++) { S += rs[i]; Q += rq[i]; }
    float mean = S * (1.0f / 1024.0f);
    float var = Q * (1.0f / 1024.0f) - mean * mean;
    float r = rsqrtf(var + 1e-6f);
    float4 sc = ((const float4*)scale)[tid];
    float4 bi = ((const float4*)bias)[tid];
    __half* o = out + (long)row * DMODEL + tid * 4;
    *(__half2*)(o) = __floats2half2_rn(
        (v.x - mean) * r * (1.0f + sc.x) + bi.x,
        (v.y - mean) * r * (1.0f + sc.y) + bi.y);
    *(__half2*)(o + 2) = __floats2half2_rn(
        (v.z - mean) * r * (1.0f + sc.z) + bi.z,
        (v.w - mean) * r * (1.0f + sc.w) + bi.w);
}

// ---------------------------------------------------------------------------
// mma.sync fp16 GEMM, 3-stage cp.async pipeline, one barrier per K-chunk.
// EPI 1: fp32 + res;  2: f16 * colscale (qkv);  3: f16 + relu
// ---------------------------------------------------------------------------
template <int EPI>
__global__ void __launch_bounds__(256, 2) gemm_mma(
    const __half* __restrict__ A, const __half* __restrict__ Bw,
    const float* __restrict__ bias, const float* __restrict__ res,
    const float* __restrict__ colscale,
    float* __restrict__ Cf, __half* __restrict__ Cs, int N, int Kp) {
    extern __shared__ char smem[];
    uint32_t sbase = s2u(smem);
    int tid = threadIdx.x;
    int wid = tid >> 5, lane = tid & 31;
    int wm = (wid & 1) * 64;
    int wn = (wid >> 1) * 32;
    long row0 = (long)blockIdx.y * 128, col0 = (long)blockIdx.x * 128;
    const __half* Ab = A + row0 * (long)Kp;
    const __half* Bb = Bw + col0 * (long)Kp;

    int ldr = tid >> 1;
    int ldc = (tid & 1) * 4;

    auto issue = [&](int c, int s) {
        long kc = (long)c << 6;
        uint32_t abase = sbase + (uint32_t)s * 32768u;
        uint32_t bbase = abase + 16384u;
        const __half* ag = Ab + (long)ldr * Kp + kc + ldc * 8;
        const __half* bg = Bb + (long)ldr * Kp + kc + ldc * 8;
#pragma unroll
        for (int i = 0; i < 4; i++) {
            uint32_t off = SW128((uint32_t)(ldr * 128 + (ldc + i) * 16));
            cpa16(abase + off, ag + i * 8);
            cpa16(bbase + off, bg + i * 8);
        }
        cpcommit();
    };

    float acc[4][4][4] = {};
    const int C = Kp >> 6;
    int st = 0;   // stage of chunk c (mod-3 counter)

    issue(0, 0);
    issue(1, 1);
    for (int c = 0; c < C; c++) {
        if (c + 1 < C)
            asm volatile("cp.async.wait_group 1;" ::: "memory");
        else
            asm volatile("cp.async.wait_group 0;" ::: "memory");
        __syncthreads();
        if (c + 2 < C) {
            int s2 = st + 2; if (s2 >= 3) s2 -= 3;
            issue(c + 2, s2);
        }
        uint32_t abase = sbase + (uint32_t)st * 32768u;
        uint32_t bbase = abase + 16384u;
#pragma unroll
        for (int ks = 0; ks < 4; ks++) {
            uint32_t a[4][4], b[2][4];
#pragma unroll
            for (int mt = 0; mt < 4; mt++) {
                int r = wm + mt * 16 + (lane & 15);
                uint32_t off = SW128((uint32_t)(r * 128 + ks * 32 + ((lane >> 4) << 4)));
                ldsm4(a[mt], abase + off);
            }
#pragma unroll
            for (int nt2 = 0; nt2 < 2; nt2++) {
                int nr = wn + nt2 * 16 + (lane & 7) + ((lane >> 4) << 3);
                uint32_t off = SW128(
                    (uint32_t)(nr * 128 + ks * 32 + (((lane >> 3) & 1) << 4)));
                ldsm4(b[nt2], bbase + off);
            }
#pragma unroll
            for (int mt = 0; mt < 4; mt++)
#pragma unroll
                for (int nt = 0; nt < 4; nt++)
                    mma_f16(acc[mt][nt], a[mt],
                            b[nt >> 1][(nt & 1) * 2], b[nt >> 1][(nt & 1) * 2 + 1]);
        }
        if (++st == 3) st = 0;
    }

    int tq = lane >> 2, tr = lane & 3;
#pragma unroll
    for (int mt = 0; mt < 4; mt++) {
#pragma unroll
        for (int half = 0; half < 2; half++) {
            long row = row0 + wm + mt * 16 + tq + half * 8;
#pragma unroll
            for (int nt = 0; nt < 4; nt++) {
                int col = (int)col0 + wn + nt * 8 + tr * 2;
                float v0 = acc[mt][nt][half * 2 + 0] + bias[col];
                float v1 = acc[mt][nt][half * 2 + 1] + bias[col + 1];
                if (EPI == 2) {
                    v0 *= colscale[col]; v1 *= colscale[col + 1];
                    *(__half2*)(Cs + row * (long)N + col) =
                        __floats2half2_rn(v0, v1);
                } else if (EPI == 3) {
                    v0 = fmaxf(v0, 0.f); v1 = fmaxf(v1, 0.f);
                    *(__half2*)(Cs + row * (long)N + col) =
                        __floats2half2_rn(v0, v1);
                } else {
                    long idx = row * (long)N + col;
                    float2 r2 = *(const float2*)(res + idx);
                    v0 += r2.x; v1 += r2.y;
                    float2 o2; o2.x = v0; o2.y = v1;
                    *(float2*)(Cf + idx) = o2;
                }
            }
        }
    }
}

// ---------------------------------------------------------------------------
// Flash attention, mma.sync fp16, 128q x 64k tiles, 3-stage KV pipeline.
// qkv layout: [b*SEQ + s][3072]; q cols 0-1023 (pre-scaled), k +1024, v +2048.
// ---------------------------------------------------------------------------
__global__ __launch_bounds__(256) void attn_mma_kernel(
    const __half* __restrict__ qkv, const float* __restrict__ mask,
    const int* __restrict__ mflags, __half* __restrict__ out) {
    extern __shared__ char smem[];
    uint32_t sb = s2u(smem);      // Q: 16KB; then 3 x (K 8KB + V 8KB)
    int tid = threadIdx.x, wid = tid >> 5, lane = tid & 31;
    int bh = blockIdx.y;
    int b = bh >> 4, h = bh & 15;
    int qt = blockIdx.x;
    int q0 = qt * 128;
    const __half* base = qkv + (long)b * SEQ * NQKV + h * 64;

    {   // Q tile (own cp.async group, completes before first wait passes)
#pragma unroll
        for (int i = 0; i < 4; i++) {
            int idx = tid * 4 + i;
            int r = idx >> 3, ch = idx & 7;
            uint32_t off = SW128((uint32_t)(r * 128 + ch * 16));
            cpa16(sb + off, base + (long)(q0 + r) * NQKV + ch * 8);
        }
        cpcommit();
    }

    auto issue_kv = [&](int c, int s) {
        uint32_t kb = sb + 16384u + (uint32_t)s * 16384u;
        uint32_t vb = kb + 8192u;
        int k0 = c * 64;
#pragma unroll
        for (int i = 0; i < 2; i++) {
            int idx = tid * 2 + i;
            int r = idx >> 3, ch = idx & 7;
            uint32_t off = SW128((uint32_t)(r * 128 + ch * 16));
            const __half* g = base + (long)(k0 + r) * NQKV + ch * 8;
            cpa16(kb + off, g + 1024);
            cpa16(vb + off, g + 2048);
        }
        cpcommit();
    };

    int wm = wid * 16;
    int tq = lane >> 2, tr = lane & 3;
    float m0 = -1e30f, m1 = -1e30f, l0 = 0.f, l1 = 0.f;
    float acc_o[8][4] = {};
    const int NT = SEQ / 64;   // 32
    int st = 0;

    issue_kv(0, 0);
    issue_kv(1, 1);
    for (int c = 0; c < NT; c++) {
        if (c + 1 < NT)
            asm volatile("cp.async.wait_group 1;" ::: "memory");
        else
            asm volatile("cp.async.wait_group 0;" ::: "memory");
        __syncthreads();
        if (c + 2 < NT) {
            int s2 = st + 2; if (s2 >= 3) s2 -= 3;
            issue_kv(c + 2, s2);
        }
        uint32_t kb = sb + 16384u + (uint32_t)st * 16384u;
        uint32_t vb = kb + 8192u;

        // ---- S = Q K^T ----
        float sf[8][4] = {};
#pragma unroll
        for (int ks = 0; ks < 4; ks++) {
            uint32_t a[4];
            {
                int r = wm + (lane & 15);
                uint32_t off = SW128((uint32_t)(r * 128 + ks * 32 + ((lane >> 4) << 4)));
                ldsm4(a, sb + off);
            }
#pragma unroll
            for (int g = 0; g < 4; g++) {
                uint32_t bf[4];
                int nr = g * 16 + (lane & 7) + ((lane >> 4) << 3);
                uint32_t off = SW128(
                    (uint32_t)(nr * 128 + ks * 32 + (((lane >> 3) & 1) << 4)));
                ldsm4(bf, kb + off);
                mma_f16(sf[2 * g], a, bf[0], bf[1]);
                mma_f16(sf[2 * g + 1], a, bf[2], bf[3]);
            }
        }

        // ---- mask (skipped when tile is all-zero) ----
        if (mflags[qt * NT + c]) {
            int k0 = c * 64;
            long r0g = (long)(q0 + wm + tq) * SEQ + k0;
            long r1g = r0g + 8L * SEQ;
#pragma unroll
            for (int nt = 0; nt < 8; nt++) {
                int key = nt * 8 + tr * 2;
                float2 mk0 = *(const float2*)&mask[r0g + key];
                float2 mk1 = *(const float2*)&mask[r1g + key];
                sf[nt][0] += mk0.x; sf[nt][1] += mk0.y;
                sf[nt][2] += mk1.x; sf[nt][3] += mk1.y;
            }
        }

        // ---- online softmax ----
        float tm0 = -1e30f, tm1 = -1e30f;
#pragma unroll
        for (int nt = 0; nt < 8; nt++) {
            tm0 = fmaxf(tm0, fmaxf(sf[nt][0], sf[nt][1]));
            tm1 = fmaxf(tm1, fmaxf(sf[nt][2], sf[nt][3]));
        }
#pragma unroll
        for (int w = 1; w <= 2; w <<= 1) {
            tm0 = fmaxf(tm0, __shfl_xor_sync(0xffffffffu, tm0, w));
            tm1 = fmaxf(tm1, __shfl_xor_sync(0xffffffffu, tm1, w));
        }
        float nm0 = fmaxf(m0, tm0), nm1 = fmaxf(m1, tm1);
        float corr0 = __expf(m0 - nm0), corr1 = __expf(m1 - nm1);
        m0 = nm0; m1 = nm1;
        float ts0 = 0.f, ts1 = 0.f;
#pragma unroll
        for (int nt = 0; nt < 8; nt++) {
            sf[nt][0] = __expf(sf[nt][0] - nm0);
            sf[nt][1] = __expf(sf[nt][1] - nm0);
            sf[nt][2] = __expf(sf[nt][2] - nm1);
            sf[nt][3] = __expf(sf[nt][3] - nm1);
            ts0 += sf[nt][0] + sf[nt][1];
            ts1 += sf[nt][2] + sf[nt][3];
        }
#pragma unroll
        for (int w = 1; w <= 2; w <<= 1) {
            ts0 += __shfl_xor_sync(0xffffffffu, ts0, w);
            ts1 += __shfl_xor_sync(0xffffffffu, ts1, w);
        }
        l0 = l0 * corr0 + ts0;
        l1 = l1 * corr1 + ts1;
#pragma unroll
        for (int nt = 0; nt < 8; nt++) {
            acc_o[nt][0] *= corr0; acc_o[nt][1] *= corr0;
            acc_o[nt][2] *= corr1; acc_o[nt][3] *= corr1;
        }

        // ---- O += P V ----
#pragma unroll
        for (int kc = 0; kc < 4; kc++) {
            uint32_t pa[4];
            pa[0] = packh(sf[2 * kc][0], sf[2 * kc][1]);
            pa[1] = packh(sf[2 * kc][2], sf[2 * kc][3]);
            pa[2] = packh(sf[2 * kc + 1][0], sf[2 * kc + 1][1]);
            pa[3] = packh(sf[2 * kc + 1][2], sf[2 * kc + 1][3]);
#pragma unroll
            for (int nb = 0; nb < 4; nb++) {
                uint32_t bf[4];
                int r = kc * 16 + (lane & 15);
                uint32_t off = SW128(
                    (uint32_t)(r * 128 + nb * 32 + ((lane >> 4) << 4)));
                ldsm4t(bf, vb + off);
                mma_f16(acc_o[2 * nb], pa, bf[0], bf[1]);
                mma_f16(acc_o[2 * nb + 1], pa, bf[2], bf[3]);
            }
        }
        if (++st == 3) st = 0;
    }

    float inv0 = 1.0f / l0, inv1 = 1.0f / l1;
    long t0 = (long)b * SEQ + q0 + wm + tq;
    __half* o0 = out + t0 * DMODEL + h * 64;
    __half* o1 = o0 + 8L * DMODEL;
#pragma unroll
    for (int nt = 0; nt < 8; nt++) {
        int col = nt * 8 + tr * 2;
        *(__half2*)(o0 + col) =
            __floats2half2_rn(acc_o[nt][0] * inv0, acc_o[nt][1] * inv0);
        *(__half2*)(o1 + col) =
            __floats2half2_rn(acc_o[nt][2] * inv1, acc_o[nt][3] * inv1);
    }
}

// ---------------------------------------------------------------------------
extern "C" void kernel_launch(void* const* d_in, const int* in_sizes, int n_in,
                              void* d_out, int out_size) {
    const float* inputs   = (const float*)d_in[0];
    const float* mask     = (const float*)d_in[1];
    const float* rmsscale = (const float*)d_in[2];
    const float* Wq = (const float*)d_in[3];
    const float* bq = (const float*)d_in[4];
    const float* Wk = (const float*)d_in[5];
    const float* bk = (const float*)d_in[6];
    const float* Wv = (const float*)d_in[7];
    const float* bv = (const float*)d_in[8];
    const float* pds = (const float*)d_in[9];
    const float* Wpost = (const float*)d_in[10];
    const float* bpost = (const float*)d_in[11];
    const float* ln_scale = (const float*)d_in[12];
    const float* ln_bias  = (const float*)d_in[13];
    const float* W1 = (const float*)d_in[14];
    const float* b1 = (const float*)d_in[15];
    const float* W2 = (const float*)d_in[16];
    const float* b2 = (const float*)d_in[17];
    float* out = (float*)d_out;

    __half *xn, *qkv, *attn, *y, *hid, *wqkv, *wpost, *w1, *w2;
    float *h, *bqkv, *colscale;
    int* mflags;
    cudaGetSymbolAddress((void**)&xn, g_xn);
    cudaGetSymbolAddress((void**)&qkv, g_qkv);
    cudaGetSymbolAddress((void**)&attn, g_attn);
    cudaGetSymbolAddress((void**)&h, g_h);
    cudaGetSymbolAddress((void**)&y, g_y);
    cudaGetSymbolAddress((void**)&hid, g_hid);
    cudaGetSymbolAddress((void**)&wqkv, g_wqkv);
    cudaGetSymbolAddress((void**)&wpost, g_wpost);
    cudaGetSymbolAddress((void**)&w1, g_w1);
    cudaGetSymbolAddress((void**)&w2, g_w2);
    cudaGetSymbolAddress((void**)&bqkv, g_bqkv);
    cudaGetSymbolAddress((void**)&colscale, g_colscale);
    cudaGetSymbolAddress((void**)&mflags, g_mflags);

    const int SMEM = 98304;   // 3 stages x 32KB
    cudaFuncSetAttribute(gemm_mma<1>, cudaFuncAttributeMaxDynamicSharedMemorySize, SMEM);
    cudaFuncSetAttribute(gemm_mma<2>, cudaFuncAttributeMaxDynamicSharedMemorySize, SMEM);
    cudaFuncSetAttribute(gemm_mma<3>, cudaFuncAttributeMaxDynamicSharedMemorySize, SMEM);
    const int ASMEM = 65536;  // Q 16KB + 3 stages x 16KB
    cudaFuncSetAttribute(attn_mma_kernel, cudaFuncAttributeMaxDynamicSharedMemorySize, ASMEM);

    // weight prep (single launch) + metadata
    conv_all_kernel<<<12288, 256>>>(Wq, Wk, Wv, Wpost, W1, W2,
                                    wqkv, wpost, w1, w2);
    qkv_meta_kernel<<<12, 256>>>(bq, bk, bv, pds, bqkv, colscale);
    mask_flags_kernel<<<512, 256>>>(mask, mflags);

    rmsnorm_kernel<<<MTOK, 256>>>(inputs, rmsscale, xn);

    // fused QKV (f16 out, q pre-scaled)
    gemm_mma<2><<<dim3(24, 64), 256, SMEM>>>(xn, wqkv, bqkv, nullptr, colscale,
                                             nullptr, qkv, NQKV, DMODEL);
    // attention
    attn_mma_kernel<<<dim3(16, 64), 256, ASMEM>>>(qkv, mask, mflags, attn);
    // post projection + residual
    gemm_mma<1><<<dim3(8, 64), 256, SMEM>>>(attn, wpost, bpost, inputs, nullptr,
                                            h, nullptr, DMODEL, DMODEL);
    layernorm_kernel<<<MTOK, 256>>>(h, ln_scale, ln_bias, y);
    // FFN single-pass fp16
    gemm_mma<3><<<dim3(32, 64), 256, SMEM>>>(y, w1, b1, nullptr, nullptr,
                                             nullptr, hid, HID, DMODEL);
    gemm_mma<1><<<dim3(8, 64), 256, SMEM>>>(hid, w2, b2, h, nullptr,
                                            out, nullptr, DMODEL, HID);
}